// round 3
// baseline (speedup 1.0000x reference)
#include <cuda_runtime.h>
#include <cuda_bf16.h>
#include <math.h>

// ------------ problem constants ------------
#define NFRM   256                  // B*T
#define ECOLS  147456               // NFRM * 576 edge columns
#define NCOLS  6144                 // NFRM * 24 node columns

// ------------ device scratch ------------
__device__ float g_edge_t[128 * ECOLS];   // transposed edge_resnet [d][col]
__device__ float g_epre  [128 * ECOLS];   // msg_We @ edge + msg_b (loop-invariant)
__device__ float g_gate  [ECOLS];
__device__ float g_node0 [128 * NCOLS];   // transposed node_resnet
__device__ float g_hnode [128 * NCOLS];
__device__ float g_nh    [128 * NCOLS];   // msg_Wh @ h_node
__device__ float g_mv    [128 * NCOLS];
__device__ float g_gi    [384 * NCOLS];
__device__ float g_gh    [384 * NCOLS];
__device__ float g_xg    [512 * NCOLS];   // lstm_Wih @ h_node + bih + bhh
__device__ float g_h     [2 * 128 * 192]; // double-buffered LSTM hidden
__device__ float g_hist  [128 * 6144];    // h history [j][t*192 + b*24 + n]
__device__ unsigned g_cnt2[8];
__device__ unsigned g_sense2[8];

__device__ __forceinline__ float sigm(float x) { return 1.f / (1.f + expf(-x)); }

__device__ __forceinline__ void ffma2(unsigned long long& acc,
                                      unsigned long long a, unsigned long long b) {
    asm("fma.rn.f32x2 %0, %1, %2, %0;" : "+l"(acc) : "l"(a), "l"(b));
}
__device__ __forceinline__ unsigned long long pack2(float x, float y) {
    unsigned long long r;
    asm("mov.b64 %0, {%1, %2};" : "=l"(r) : "f"(x), "f"(y));
    return r;
}
__device__ __forceinline__ float2 unpack2(unsigned long long v) {
    float2 f;
    asm("mov.b64 {%0, %1}, %2;" : "=f"(f.x), "=f"(f.y) : "l"(v));
    return f;
}

// ------------ transposes (float4) ------------
__global__ void __launch_bounds__(256) tr_edge_k(const float* __restrict__ in)
{
    int o4 = blockIdx.x * 256 + threadIdx.x;         // < 128*ECOLS/4
    int d = o4 / 36864; int c4 = o4 - d * 36864;
    int f = c4 / 144;   int vw4 = c4 - f * 144;
    float4 v = *(const float4*)(in + f * 73728 + d * 576 + vw4 * 4);
    *(float4*)(g_edge_t + d * ECOLS + f * 576 + vw4 * 4) = v;
}

__global__ void __launch_bounds__(256) tr_node_k(const float* __restrict__ in)
{
    int o4 = blockIdx.x * 256 + threadIdx.x;         // < 128*NCOLS/4
    int d = o4 / 1536; int c4 = o4 - d * 1536;
    int f = c4 / 6;    int n4 = c4 - f * 6;
    float4 v = *(const float4*)(in + f * 3072 + d * 24 + n4 * 4);
    int dst = d * NCOLS + f * 24 + n4 * 4;
    *(float4*)(g_node0 + dst) = v;
    *(float4*)(g_hnode + dst) = v;
}

// ------------ SGEMM v2: Y[M,cols] = W[M,128] @ X[128,cols] (+bias,+bias2) ------------
// grid (cols/64, M/128), block 256; thread = 8 rows x 4 cols; f32x2 row-pair vectorized.
__global__ void __launch_bounds__(256) sgemm2_k(const float* __restrict__ W,
                                                const float* __restrict__ X,
                                                const float* __restrict__ bias,
                                                const float* __restrict__ bias2,
                                                float* __restrict__ Y, int cols)
{
    __shared__ __align__(16) float sW[32][136];      // K-major: sW[k][row]
    __shared__ __align__(16) float sX[32][68];
    int tid = threadIdx.x;
    int c0 = blockIdx.x * 64;
    int m0 = blockIdx.y * 128;
    int tx = tid & 15, ty = tid >> 4;
    unsigned long long acc[4][4];
#pragma unroll
    for (int p = 0; p < 4; p++)
#pragma unroll
        for (int c = 0; c < 4; c++) acc[p][c] = 0ull;

    for (int kt = 0; kt < 4; kt++) {
#pragma unroll
        for (int i = 0; i < 4; i++) {                // 1024 float4 of W tile -> transposed
            int idx = tid + i * 256;
            int row = idx & 127;
            int kq  = (idx >> 7) << 2;
            float4 v = *(const float4*)(W + (m0 + row) * 128 + kt * 32 + kq);
            sW[kq][row] = v.x; sW[kq + 1][row] = v.y;
            sW[kq + 2][row] = v.z; sW[kq + 3][row] = v.w;
        }
#pragma unroll
        for (int i = 0; i < 2; i++) {
            int idx = tid + i * 256;
            int k = idx >> 4, j = (idx & 15) << 2;
            *(float4*)&sX[k][j] = *(const float4*)(X + (kt * 32 + k) * cols + c0 + j);
        }
        __syncthreads();
#pragma unroll
        for (int k = 0; k < 32; k++) {
            ulonglong2 aA = *(const ulonglong2*)&sW[k][ty * 8];
            ulonglong2 aB = *(const ulonglong2*)&sW[k][ty * 8 + 4];
            float4 bq = *(const float4*)&sX[k][tx << 2];
            unsigned long long b0 = pack2(bq.x, bq.x);
            unsigned long long b1 = pack2(bq.y, bq.y);
            unsigned long long b2 = pack2(bq.z, bq.z);
            unsigned long long b3 = pack2(bq.w, bq.w);
            ffma2(acc[0][0], aA.x, b0); ffma2(acc[0][1], aA.x, b1);
            ffma2(acc[0][2], aA.x, b2); ffma2(acc[0][3], aA.x, b3);
            ffma2(acc[1][0], aA.y, b0); ffma2(acc[1][1], aA.y, b1);
            ffma2(acc[1][2], aA.y, b2); ffma2(acc[1][3], aA.y, b3);
            ffma2(acc[2][0], aB.x, b0); ffma2(acc[2][1], aB.x, b1);
            ffma2(acc[2][2], aB.x, b2); ffma2(acc[2][3], aB.x, b3);
            ffma2(acc[3][0], aB.y, b0); ffma2(acc[3][1], aB.y, b1);
            ffma2(acc[3][2], aB.y, b2); ffma2(acc[3][3], aB.y, b3);
        }
        __syncthreads();
    }
#pragma unroll
    for (int r = 0; r < 8; r++) {
        int row = m0 + ty * 8 + r;
        float bs = (bias ? bias[row] : 0.f) + (bias2 ? bias2[row] : 0.f);
        int p = r >> 1;
        float4 o;
        if (r & 1) {
            o.x = unpack2(acc[p][0]).y + bs; o.y = unpack2(acc[p][1]).y + bs;
            o.z = unpack2(acc[p][2]).y + bs; o.w = unpack2(acc[p][3]).y + bs;
        } else {
            o.x = unpack2(acc[p][0]).x + bs; o.y = unpack2(acc[p][1]).x + bs;
            o.z = unpack2(acc[p][2]).x + bs; o.w = unpack2(acc[p][3]).x + bs;
        }
        *(float4*)(Y + row * cols + c0 + (tx << 2)) = o;
    }
}

// ------------ fused link: gate = pair_mask * sigmoid(W2 . relu(W1@X + b1) + b2) ------------
// RECON=false: X = E (edge_t).  RECON=true: X = gate_prev * relu(nh_prev + epre) on the fly.
template <bool RECON>
__global__ void __launch_bounds__(256) link2_k(const float* __restrict__ E,
                                               const float* __restrict__ W1,
                                               const float* __restrict__ b1,
                                               const float* __restrict__ W2,
                                               const float* __restrict__ b2p,
                                               const int* __restrict__ nnum)
{
    __shared__ __align__(16) float sW[32][136];
    __shared__ __align__(16) float sX[32][68];
    __shared__ float snh[128][25];
    __shared__ float sgate[64];
    __shared__ float sRed[16][64];
    int tid = threadIdx.x;
    int c0 = blockIdx.x * 64;
    int f = c0 / 576;                                // 576 % 64 == 0: block within one frame
    int tx = tid & 15, ty = tid >> 4;

    if (RECON) {
        for (int i = tid; i < 3072; i += 256) {
            int d = i / 24, w = i - d * 24;
            snh[d][w] = g_nh[d * NCOLS + f * 24 + w];
        }
        if (tid < 64) sgate[tid] = g_gate[c0 + tid];
        __syncthreads();
    }

    unsigned long long acc[4][4];
#pragma unroll
    for (int p = 0; p < 4; p++)
#pragma unroll
        for (int c = 0; c < 4; c++) acc[p][c] = 0ull;

    for (int kt = 0; kt < 4; kt++) {
#pragma unroll
        for (int i = 0; i < 4; i++) {
            int idx = tid + i * 256;
            int row = idx & 127;
            int kq  = (idx >> 7) << 2;
            float4 v = *(const float4*)(W1 + row * 128 + kt * 32 + kq);
            sW[kq][row] = v.x; sW[kq + 1][row] = v.y;
            sW[kq + 2][row] = v.z; sW[kq + 3][row] = v.w;
        }
#pragma unroll
        for (int i = 0; i < 2; i++) {
            int idx = tid + i * 256;
            int k = idx >> 4, j = (idx & 15) << 2;
            int kg = kt * 32 + k;
            float4 e = *(const float4*)(E + kg * ECOLS + c0 + j);
            if (RECON) {
                int rb = (c0 + j) % 24;
                int w1 = rb + 1; if (w1 >= 24) w1 -= 24;
                int w2 = rb + 2; if (w2 >= 24) w2 -= 24;
                int w3 = rb + 3; if (w3 >= 24) w3 -= 24;
                e.x = sgate[j + 0] * fmaxf(snh[kg][rb] + e.x, 0.f);
                e.y = sgate[j + 1] * fmaxf(snh[kg][w1] + e.y, 0.f);
                e.z = sgate[j + 2] * fmaxf(snh[kg][w2] + e.z, 0.f);
                e.w = sgate[j + 3] * fmaxf(snh[kg][w3] + e.w, 0.f);
            }
            *(float4*)&sX[k][j] = e;
        }
        __syncthreads();
#pragma unroll
        for (int k = 0; k < 32; k++) {
            ulonglong2 aA = *(const ulonglong2*)&sW[k][ty * 8];
            ulonglong2 aB = *(const ulonglong2*)&sW[k][ty * 8 + 4];
            float4 bq = *(const float4*)&sX[k][tx << 2];
            unsigned long long b0 = pack2(bq.x, bq.x);
            unsigned long long b1v = pack2(bq.y, bq.y);
            unsigned long long b2v = pack2(bq.z, bq.z);
            unsigned long long b3 = pack2(bq.w, bq.w);
            ffma2(acc[0][0], aA.x, b0); ffma2(acc[0][1], aA.x, b1v);
            ffma2(acc[0][2], aA.x, b2v); ffma2(acc[0][3], aA.x, b3);
            ffma2(acc[1][0], aA.y, b0); ffma2(acc[1][1], aA.y, b1v);
            ffma2(acc[1][2], aA.y, b2v); ffma2(acc[1][3], aA.y, b3);
            ffma2(acc[2][0], aB.x, b0); ffma2(acc[2][1], aB.x, b1v);
            ffma2(acc[2][2], aB.x, b2v); ffma2(acc[2][3], aB.x, b3);
            ffma2(acc[3][0], aB.y, b0); ffma2(acc[3][1], aB.y, b1v);
            ffma2(acc[3][2], aB.y, b2v); ffma2(acc[3][3], aB.y, b3);
        }
        __syncthreads();
    }

    // epilogue: relu + dot with W2, partials across ty groups
    float part[4] = {0.f, 0.f, 0.f, 0.f};
#pragma unroll
    for (int p = 0; p < 4; p++) {
        int r0 = ty * 8 + 2 * p;
        float bb0 = b1[r0], bb1 = b1[r0 + 1];
        float w20 = W2[r0], w21 = W2[r0 + 1];
#pragma unroll
        for (int c = 0; c < 4; c++) {
            float2 u = unpack2(acc[p][c]);
            part[c] += fmaxf(u.x + bb0, 0.f) * w20 + fmaxf(u.y + bb1, 0.f) * w21;
        }
    }
#pragma unroll
    for (int c = 0; c < 4; c++) sRed[ty][(tx << 2) + c] = part[c];
    __syncthreads();
    if (tid < 64) {
        float s = 0.f;
#pragma unroll
        for (int y = 0; y < 16; y++) s += sRed[y][tid];
        int col = c0 + tid;
        int rem = col - f * 576;
        int v = rem / 24;  int w = rem - v * 24;
        int cnt = nnum[f];
        g_gate[col] = (v < cnt && w < cnt) ? sigm(s + b2p[0]) : 0.f;
    }
}

// ------------ message aggregation: m_v only (h_edge never materialized) ------------
// one block per frame; 8 warps; lane = sender w.
__global__ void __launch_bounds__(256) msg2_k()
{
    __shared__ float snh[128][25];
    __shared__ float sg[576];
    int f = blockIdx.x;
    int tid = threadIdx.x;
    for (int i = tid; i < 3072; i += 256) {
        int d = i / 24, w = i - d * 24;
        snh[d][w] = g_nh[d * NCOLS + f * 24 + w];
    }
    for (int i = tid; i < 576; i += 256) sg[i] = g_gate[f * 576 + i];
    __syncthreads();

    int wl = tid & 31, wp = tid >> 5;
    bool ok = wl < 24;
    for (int v = 0; v < 24; v++) {
        int base = f * 576 + v * 24;
        float gw = ok ? sg[v * 24 + wl] : 0.f;
#pragma unroll 4
        for (int i = 0; i < 16; i++) {
            int d = wp * 16 + i;
            float s = 0.f;
            if (ok) s = gw * fmaxf(snh[d][wl] + g_epre[d * ECOLS + base + wl], 0.f);
#pragma unroll
            for (int o = 16; o; o >>= 1) s += __shfl_xor_sync(0xffffffffu, s, o);
            if (wl == 0) g_mv[d * NCOLS + f * 24 + v] = s;
        }
    }
}

// ------------ GRU elementwise ------------
__global__ void __launch_bounds__(256) gru_k(const int* __restrict__ nnum)
{
    int idx = blockIdx.x * 256 + threadIdx.x;        // < 128*NCOLS
    int j = idx / NCOLS; int col = idx - j * NCOLS;
    float gir = g_gi[j * NCOLS + col];
    float giz = g_gi[(128 + j) * NCOLS + col];
    float gin = g_gi[(256 + j) * NCOLS + col];
    float ghr = g_gh[j * NCOLS + col];
    float ghz = g_gh[(128 + j) * NCOLS + col];
    float ghn = g_gh[(256 + j) * NCOLS + col];
    float r = sigm(gir + ghr);
    float z = sigm(giz + ghz);
    float n2 = tanhf(gin + r * ghn);
    float h = g_hnode[idx];
    float hn = (1.f - z) * n2 + z * h;
    int f = col / 24; int n = col - f * 24;
    g_hnode[idx] = (n < nnum[f]) ? hn : g_node0[idx];
}

// ------------ persistent LSTM: all 32 timesteps, per-batch grid barrier ------------
// grid 128 (rg = blk & 15 owns 8 hidden rows; b = blk >> 4), 192 threads.
__device__ __forceinline__ void group_barrier(int b, unsigned want)
{
    __threadfence();
    __syncthreads();
    if (threadIdx.x == 0) {
        unsigned tk = atomicAdd(&g_cnt2[b], 1u);
        if (tk == 15u) {
            g_cnt2[b] = 0;
            __threadfence();
            atomicExch(&g_sense2[b], want);
        } else {
            unsigned v;
            do {
                asm volatile("ld.acquire.gpu.u32 %0, [%1];" : "=r"(v) : "l"(&g_sense2[b]));
            } while (v != want);
        }
    }
    __syncthreads();
}

__global__ void __launch_bounds__(192) lstm_all_k(const float* __restrict__ Whh)
{
    __shared__ __align__(16) float sWt[128][36];     // K-major Whh slice
    __shared__ float sH[128][25];
    __shared__ float sG[32][25];
    int tid = threadIdx.x;
    int rg = blockIdx.x & 15, b = blockIdx.x >> 4;

    for (int i = tid; i < 4096; i += 192) {
        int r = i >> 7, k = i & 127;
        int jg = (r >> 3) * 128 + rg * 8 + (r & 7);
        sWt[k][r] = Whh[jg * 128 + k];
    }
    int tr = tid & 7, tc = tid >> 3;                 // gemm mapping: 4 rows x 1 col
    int hh = tid / 24, nn = tid - hh * 24;           // update mapping
    int jrow = rg * 8 + hh;
    int scol = b * 24 + nn;
    float creg = 0.f;
    unsigned phase = 0;

    for (int t = 0; t < 32; t++) {
        if (t == 0) {
            for (int i = tid; i < 3200; i += 192) (&sH[0][0])[i] = 0.f;
            __syncthreads();
        } else {
            phase++;
            group_barrier(b, phase & 1u);
            const float* hb = g_h + ((t + 1) & 1) * 24576;
            for (int i = tid; i < 3072; i += 192) {
                int j = i / 24, n2 = i - j * 24;
                sH[j][n2] = __ldcg(hb + j * 192 + b * 24 + n2);
            }
            __syncthreads();
        }

        unsigned long long acc0 = 0ull, acc1 = 0ull;
#pragma unroll 8
        for (int k = 0; k < 128; k++) {
            ulonglong2 av = *(const ulonglong2*)&sWt[k][tr * 4];
            float bv = sH[k][tc];
            unsigned long long bs = pack2(bv, bv);
            ffma2(acc0, av.x, bs);
            ffma2(acc1, av.y, bs);
        }
        float2 u0 = unpack2(acc0), u1 = unpack2(acc1);
        sG[tr * 4 + 0][tc] = u0.x; sG[tr * 4 + 1][tc] = u0.y;
        sG[tr * 4 + 2][tc] = u1.x; sG[tr * 4 + 3][tc] = u1.y;
        __syncthreads();

        int colx = (b * 32 + t) * 24 + nn;
        float ig = sG[hh][nn]      + g_xg[(      jrow) * NCOLS + colx];
        float fg = sG[8 + hh][nn]  + g_xg[(128 + jrow) * NCOLS + colx];
        float gg = sG[16 + hh][nn] + g_xg[(256 + jrow) * NCOLS + colx];
        float og = sG[24 + hh][nn] + g_xg[(384 + jrow) * NCOLS + colx];
        creg = sigm(fg) * creg + sigm(ig) * tanhf(gg);
        float hnew = sigm(og) * tanhf(creg);
        __stcg(g_h + (t & 1) * 24576 + jrow * 192 + scol, hnew);
        g_hist[jrow * 6144 + t * 192 + scol] = hnew;
        __syncthreads();                              // protect sG before next gemm at t==0 path
    }
    phase++;
    group_barrier(b, phase & 1u);                     // even total flips -> replay-safe
}

// ------------ readout: out = (hist^T @ roW^T + rob) * mask ------------
__global__ void __launch_bounds__(256) readout_k(const float* __restrict__ roW,
                                                 const float* __restrict__ rob,
                                                 const int* __restrict__ nnum,
                                                 float* __restrict__ out)
{
    __shared__ float sH[128][65];
    __shared__ float sRo[6][128];
    __shared__ float sRob[6];
    int tid = threadIdx.x;
    int c0 = blockIdx.x * 64;
    for (int i = tid; i < 8192; i += 256) {
        int j = i >> 6, cc = i & 63;
        sH[j][cc] = g_hist[j * 6144 + c0 + cc];
    }
    for (int i = tid; i < 768; i += 256) sRo[i >> 7][i & 127] = roW[i];
    if (tid < 6) sRob[tid] = rob[tid];
    __syncthreads();
    for (int e = tid; e < 384; e += 256) {
        int cc = e / 6, c = e - cc * 6;
        float s = 0.f;
#pragma unroll 8
        for (int j = 0; j < 128; j++) s += sRo[c][j] * sH[j][cc];
        int ct = c0 + cc;
        int t = ct / 192; int srem = ct - t * 192;
        int b = srem / 24; int n = srem - b * 24;
        int f = b * 32 + t;
        out[(f * 24 + n) * 6 + c] = (n < nnum[f]) ? (s + sRob[c]) : 0.f;
    }
}

// ------------ host launcher ------------
extern "C" void kernel_launch(void* const* d_in, const int* in_sizes, int n_in,
                              void* d_out, int out_size)
{
    const float* node     = (const float*)d_in[0];
    const float* edge     = (const float*)d_in[1];
    const float* link_W1  = (const float*)d_in[2];
    const float* link_b1  = (const float*)d_in[3];
    const float* link_W2  = (const float*)d_in[4];
    const float* link_b2  = (const float*)d_in[5];
    const float* msg_Wh   = (const float*)d_in[6];
    const float* msg_We   = (const float*)d_in[7];
    const float* msg_b    = (const float*)d_in[8];
    const float* gru_Wih  = (const float*)d_in[9];
    const float* gru_Whh  = (const float*)d_in[10];
    const float* gru_bih  = (const float*)d_in[11];
    const float* gru_bhh  = (const float*)d_in[12];
    const float* lstm_Wih = (const float*)d_in[13];
    const float* lstm_Whh = (const float*)d_in[14];
    const float* lstm_bih = (const float*)d_in[15];
    const float* lstm_bhh = (const float*)d_in[16];
    const float* ro_W     = (const float*)d_in[17];
    const float* ro_b     = (const float*)d_in[18];
    const int*   nnum     = (const int*)d_in[19];
    float* out = (float*)d_out;

    float* edge_t; cudaGetSymbolAddress((void**)&edge_t, g_edge_t);
    float* epre;   cudaGetSymbolAddress((void**)&epre,   g_epre);
    float* hnode;  cudaGetSymbolAddress((void**)&hnode,  g_hnode);
    float* nh;     cudaGetSymbolAddress((void**)&nh,     g_nh);
    float* mv;     cudaGetSymbolAddress((void**)&mv,     g_mv);
    float* gi;     cudaGetSymbolAddress((void**)&gi,     g_gi);
    float* gh;     cudaGetSymbolAddress((void**)&gh,     g_gh);
    float* xg;     cudaGetSymbolAddress((void**)&xg,     g_xg);

    tr_edge_k<<<(128 * ECOLS / 4) / 256, 256>>>(edge);
    tr_node_k<<<(128 * NCOLS / 4) / 256, 256>>>(node);

    // loop-invariant: epre = msg_We @ edge_t + msg_b
    sgemm2_k<<<dim3(ECOLS / 64, 1), 256>>>(msg_We, edge_t, msg_b, nullptr, epre, ECOLS);

    for (int p = 0; p < 3; p++) {
        if (p == 0)
            link2_k<false><<<ECOLS / 64, 256>>>(edge_t, link_W1, link_b1, link_W2, link_b2, nnum);
        else
            link2_k<true><<<ECOLS / 64, 256>>>(epre, link_W1, link_b1, link_W2, link_b2, nnum);
        sgemm2_k<<<dim3(NCOLS / 64, 1), 256>>>(msg_Wh, hnode, nullptr, nullptr, nh, NCOLS);
        msg2_k<<<NFRM, 256>>>();
        sgemm2_k<<<dim3(NCOLS / 64, 3), 256>>>(gru_Wih, mv,    gru_bih, nullptr, gi, NCOLS);
        sgemm2_k<<<dim3(NCOLS / 64, 3), 256>>>(gru_Whh, hnode, gru_bhh, nullptr, gh, NCOLS);
        gru_k<<<(128 * NCOLS) / 256, 256>>>(nnum);
    }

    // LSTM input projection for all timesteps, biases folded
    sgemm2_k<<<dim3(NCOLS / 64, 4), 256>>>(lstm_Wih, hnode, lstm_bih, lstm_bhh, xg, NCOLS);

    lstm_all_k<<<128, 192>>>(lstm_Whh);

    readout_k<<<96, 256>>>(ro_W, ro_b, nnum, out);
    (void)in_sizes; (void)n_in; (void)out_size;
}

// round 5
// speedup vs baseline: 1.8926x; 1.8926x over previous
#include <cuda_runtime.h>
#include <cuda_bf16.h>
#include <math.h>
#include <stdint.h>

// ------------ problem constants ------------
#define NFRM   256                  // B*T
#define ECOLS  147456               // NFRM * 576 edge columns
#define NCOLS  6144                 // NFRM * 24 node columns

// ------------ device scratch ------------
__device__ float g_epre  [128 * ECOLS];   // msg_We @ edge + msg_b (loop-invariant)
__device__ float g_gate  [ECOLS];
__device__ float g_node0 [128 * NCOLS];   // transposed node_resnet
__device__ float g_hnode [128 * NCOLS];
__device__ float g_nh    [128 * NCOLS];   // msg_Wh @ h_node
__device__ float g_mv    [128 * NCOLS];
__device__ float g_gi    [384 * NCOLS];
__device__ float g_gh    [384 * NCOLS];
__device__ float g_xg    [512 * NCOLS];   // lstm_Wih @ h_node + bih + bhh
__device__ float g_h     [2 * 128 * 192]; // double-buffered LSTM hidden
__device__ float g_hist  [128 * 6144];    // h history [j][t*192 + b*24 + n]
__device__ unsigned g_cnt2[8];
__device__ unsigned g_sense2[8];
__device__ unsigned g_wA [2 * 24576];     // HMMA A-fragments: [0]=link_W1, [1]=msg_We

__device__ __forceinline__ float sigm(float x) { return 1.f / (1.f + expf(-x)); }

__device__ __forceinline__ void ffma2(unsigned long long& acc,
                                      unsigned long long a, unsigned long long b) {
    asm("fma.rn.f32x2 %0, %1, %2, %0;" : "+l"(acc) : "l"(a), "l"(b));
}
__device__ __forceinline__ unsigned long long pack2(float x, float y) {
    unsigned long long r;
    asm("mov.b64 %0, {%1, %2};" : "=l"(r) : "f"(x), "f"(y));
    return r;
}
__device__ __forceinline__ float2 unpack2(unsigned long long v) {
    float2 f;
    asm("mov.b64 {%0, %1}, %2;" : "=f"(f.x), "=f"(f.y) : "l"(v));
    return f;
}

__device__ __forceinline__ void split_bf(float x, __nv_bfloat16& h, __nv_bfloat16& l) {
    h = __float2bfloat16(x);
    l = __float2bfloat16(x - __bfloat162float(h));
}

// ---- HMMA m16n8k16 bf16 (portable PTX, works on plain sm_103) ----
__device__ __forceinline__ void mma_bf16(float* c, uint32_t a0, uint32_t a1,
                                         uint32_t a2, uint32_t a3,
                                         uint32_t b0, uint32_t b1) {
    asm volatile(
        "mma.sync.aligned.m16n8k16.row.col.f32.bf16.bf16.f32 "
        "{%0,%1,%2,%3}, {%4,%5,%6,%7}, {%8,%9}, {%0,%1,%2,%3};"
        : "+f"(c[0]), "+f"(c[1]), "+f"(c[2]), "+f"(c[3])
        : "r"(a0), "r"(a1), "r"(a2), "r"(a3), "r"(b0), "r"(b1));
}

// dynamic smem layout for edge kernels
#define SB_OFF    0        // bf16 [96][392] = 75264 B   (word pitch 196 -> conflict-free)
#define SNH_OFF   75264    // float [128*24] = 12288 B
#define SG_OFF    87552    // float [96]
#define SRED_OFF  87936    // float [8][104] = 3328 B
#define SM_BYTES  91264
#define BPITCHW   196      // 32-bit words per B row

// ------------ prep: pack W (split-bf16, K-stacked 384) into HMMA A-frag layout ------------
// storage: g_wA_region[((mblk*24 + kk)*32 + lane)*4 + r], 6144 threads, each one uint4
__global__ void __launch_bounds__(256) prep_w_k(const float* __restrict__ W, unsigned* __restrict__ out)
{
    int gidx = blockIdx.x * 256 + threadIdx.x;       // < 6144
    int mblk = gidx / 768;
    int rem  = gidx - mblk * 768;
    int kk   = rem >> 5;
    int lane = rem & 31;
    int g = lane >> 2, t = lane & 3;

    unsigned regs[4];
#pragma unroll
    for (int r = 0; r < 4; r++) {
        int row = mblk * 16 + g + ((r & 1) ? 8 : 0);
        int k0  = kk * 16 + t * 2 + ((r & 2) ? 8 : 0);
        unsigned pk = 0;
#pragma unroll
        for (int e = 0; e < 2; e++) {
            int ks = k0 + e;
            int region = ks >> 7;
            int kloc = ks & 127;
            float w = W[row * 128 + kloc];
            __nv_bfloat16 h, l; split_bf(w, h, l);
            __nv_bfloat16 b = (region < 2) ? h : l;
            pk |= (unsigned)__bfloat16_as_ushort(b) << (e * 16);
        }
        regs[r] = pk;
    }
    *(uint4*)(out + gidx * 4) = make_uint4(regs[0], regs[1], regs[2], regs[3]);
}

// ------------ warp GEMM pass: C[12][4] += A(warp mblk) @ B(smem) over K=384 ------------
__device__ __forceinline__ void gemm_pass(float c[12][4], const uint4* __restrict__ A4,
                                          const uint32_t* __restrict__ sB32,
                                          int mblk, int lane)
{
    int g = lane >> 2, t = lane & 3;
#pragma unroll
    for (int nt = 0; nt < 12; nt++)
#pragma unroll
        for (int r = 0; r < 4; r++) c[nt][r] = 0.f;

    for (int kk = 0; kk < 24; kk++) {
        uint4 a = A4[(mblk * 24 + kk) * 32 + lane];
        const uint32_t* bp = sB32 + g * BPITCHW + kk * 8 + t;
#pragma unroll
        for (int nt = 0; nt < 12; nt++) {
            uint32_t b0 = bp[nt * 8 * BPITCHW];
            uint32_t b1 = bp[nt * 8 * BPITCHW + 4];
            mma_bf16(c[nt], a.x, a.y, a.z, a.w, b0, b1);
        }
    }
}

// ------------ gate epilogue: gate[c0+n] = mask * sigm(sum_m relu(C[m][n]+b1[m])*W2[m] + b2) ------------
__device__ __forceinline__ void gate_epi(float c[12][4], char* smem,
                                         const float* __restrict__ lb1,
                                         const float* __restrict__ W2,
                                         const float* __restrict__ b2p,
                                         const int* __restrict__ nnum,
                                         int c0, int f, int off)
{
    int tid = threadIdx.x;
    int mblk = tid >> 5, lane = tid & 31;
    int g = lane >> 2, t = lane & 3;
    int r0 = mblk * 16 + g;
    float bb0 = lb1[r0], bb8 = lb1[r0 + 8];
    float w0 = W2[r0], w8 = W2[r0 + 8];
    float* sRed = (float*)(smem + SRED_OFF);

    float p0[12], p1[12];
#pragma unroll
    for (int nt = 0; nt < 12; nt++) {
        p0[nt] = fmaxf(c[nt][0] + bb0, 0.f) * w0 + fmaxf(c[nt][2] + bb8, 0.f) * w8;
        p1[nt] = fmaxf(c[nt][1] + bb0, 0.f) * w0 + fmaxf(c[nt][3] + bb8, 0.f) * w8;
    }
#pragma unroll
    for (int nt = 0; nt < 12; nt++) {
#pragma unroll
        for (int m = 4; m <= 16; m <<= 1) {
            p0[nt] += __shfl_xor_sync(0xffffffffu, p0[nt], m);
            p1[nt] += __shfl_xor_sync(0xffffffffu, p1[nt], m);
        }
    }
    if (g == 0) {
#pragma unroll
        for (int nt = 0; nt < 12; nt++) {
            sRed[mblk * 104 + nt * 8 + t * 2]     = p0[nt];
            sRed[mblk * 104 + nt * 8 + t * 2 + 1] = p1[nt];
        }
    }
    __syncthreads();
    if (tid < 96) {
        float s = 0.f;
#pragma unroll
        for (int w = 0; w < 8; w++) s += sRed[w * 104 + tid];
        int v = (off + tid) / 24, ww = (off + tid) - v * 24;
        int cnt = nnum[f];
        g_gate[c0 + tid] = (v < cnt && ww < cnt) ? sigm(s + b2p[0]) : 0.f;
    }
}

// ------------ edge0_k: layer-0 gate + epre (two GEMM passes share one B tile) ------------
__global__ void __launch_bounds__(256) edge0_k(const float* __restrict__ edge,
                                               const float* __restrict__ lb1,
                                               const float* __restrict__ W2,
                                               const float* __restrict__ b2p,
                                               const float* __restrict__ msg_b,
                                               const int* __restrict__ nnum)
{
    extern __shared__ char smem[];
    int tid = threadIdx.x;
    int c0 = blockIdx.x * 96;
    int f = c0 / 576;
    int off = c0 - f * 576;
    __nv_bfloat16* sBh = (__nv_bfloat16*)(smem + SB_OFF);
    const uint32_t* sB32 = (const uint32_t*)(smem + SB_OFF);

    // B conversion from original edge layout: rows d = k, cols n
    {
        int d = tid & 127, half = tid >> 7;
        const float* src = edge + (size_t)f * 73728 + d * 576 + off + half * 48;
        for (int i = 0; i < 48; i += 4) {
            float4 x = *(const float4*)(src + i);
            float xs[4] = {x.x, x.y, x.z, x.w};
#pragma unroll
            for (int j = 0; j < 4; j++) {
                int n = half * 48 + i + j;
                __nv_bfloat16 h, l; split_bf(xs[j], h, l);
                sBh[n * 392 + d]       = h;
                sBh[n * 392 + 128 + d] = l;
                sBh[n * 392 + 256 + d] = h;
            }
        }
    }
    __syncthreads();

    int mblk = tid >> 5, lane = tid & 31;
    int g = lane >> 2, t = lane & 3;
    float c[12][4];

    // pass 1: link_W1 -> gate0
    gemm_pass(c, (const uint4*)(g_wA), sB32, mblk, lane);
    gate_epi(c, smem, lb1, W2, b2p, nnum, c0, f, off);
    __syncthreads();

    // pass 2: msg_We -> epre
    gemm_pass(c, (const uint4*)(g_wA + 24576), sB32, mblk, lane);
    {
        int r0 = mblk * 16 + g;
        float mb0 = msg_b[r0], mb8 = msg_b[r0 + 8];
#pragma unroll
        for (int nt = 0; nt < 12; nt++) {
            int col = c0 + nt * 8 + t * 2;
            *(float2*)(g_epre + (size_t)r0 * ECOLS + col) =
                make_float2(c[nt][0] + mb0, c[nt][1] + mb0);
            *(float2*)(g_epre + (size_t)(r0 + 8) * ECOLS + col) =
                make_float2(c[nt][2] + mb8, c[nt][3] + mb8);
        }
    }
}

// ------------ recon_k: layer p>=1 gate + m_v of layer p-1 (byproduct) ------------
__global__ void __launch_bounds__(256) recon_k(const float* __restrict__ lb1,
                                               const float* __restrict__ W2,
                                               const float* __restrict__ b2p,
                                               const int* __restrict__ nnum)
{
    extern __shared__ char smem[];
    int tid = threadIdx.x;
    int c0 = blockIdx.x * 96;
    int f = c0 / 576;
    int off = c0 - f * 576;
    __nv_bfloat16* sBh = (__nv_bfloat16*)(smem + SB_OFF);
    const uint32_t* sB32 = (const uint32_t*)(smem + SB_OFF);
    float* snh = (float*)(smem + SNH_OFF);   // [128][24]
    float* sg  = (float*)(smem + SG_OFF);    // [96]

    for (int i = tid; i < 3072; i += 256) {
        int d = i / 24, w = i - d * 24;
        snh[d * 24 + w] = g_nh[d * NCOLS + f * 24 + w];
    }
    if (tid < 96) sg[tid] = g_gate[c0 + tid];
    __syncthreads();

    // B conversion from reconstruction h_edge = gate * relu(nh + epre); m_v byproduct
    {
        int d = tid & 127, half = tid >> 7;
        const float* esrc = g_epre + (size_t)d * ECOLS + c0 + half * 48;
        float s0 = 0.f, s1 = 0.f;
        for (int i = 0; i < 48; i += 4) {
            float4 x = *(const float4*)(esrc + i);
            float xs[4] = {x.x, x.y, x.z, x.w};
#pragma unroll
            for (int j = 0; j < 4; j++) {
                int n = half * 48 + i + j;
                int w = n % 24;
                float val = sg[n] * fmaxf(snh[d * 24 + w] + xs[j], 0.f);
                if (i + j < 24) s0 += val; else s1 += val;
                __nv_bfloat16 h, l; split_bf(val, h, l);
                sBh[n * 392 + d]       = h;
                sBh[n * 392 + 128 + d] = l;
                sBh[n * 392 + 256 + d] = h;
            }
        }
        int vb = off / 24 + half * 2;
        g_mv[d * NCOLS + f * 24 + vb]     = s0;
        g_mv[d * NCOLS + f * 24 + vb + 1] = s1;
    }
    __syncthreads();

    int mblk = tid >> 5, lane = tid & 31;
    float c[12][4];
    gemm_pass(c, (const uint4*)(g_wA), sB32, mblk, lane);
    gate_epi(c, smem, lb1, W2, b2p, nnum, c0, f, off);
}

// ------------ node transpose ------------
__global__ void __launch_bounds__(256) tr_node_k(const float* __restrict__ in)
{
    int o4 = blockIdx.x * 256 + threadIdx.x;         // < 128*NCOLS/4
    int d = o4 / 1536; int c4 = o4 - d * 1536;
    int f = c4 / 6;    int n4 = c4 - f * 6;
    float4 v = *(const float4*)(in + f * 3072 + d * 24 + n4 * 4);
    int dst = d * NCOLS + f * 24 + n4 * 4;
    *(float4*)(g_node0 + dst) = v;
    *(float4*)(g_hnode + dst) = v;
}

// ------------ SGEMM (node-sized): Y[M,cols] = W[M,128] @ X[128,cols] ------------
__global__ void __launch_bounds__(256) sgemm2_k(const float* __restrict__ W,
                                                const float* __restrict__ X,
                                                const float* __restrict__ bias,
                                                const float* __restrict__ bias2,
                                                float* __restrict__ Y, int cols)
{
    __shared__ __align__(16) float sW[32][136];
    __shared__ __align__(16) float sX[32][68];
    int tid = threadIdx.x;
    int c0 = blockIdx.x * 64;
    int m0 = blockIdx.y * 128;
    int tx = tid & 15, ty = tid >> 4;
    unsigned long long acc[4][4];
#pragma unroll
    for (int p = 0; p < 4; p++)
#pragma unroll
        for (int c = 0; c < 4; c++) acc[p][c] = 0ull;

    for (int kt = 0; kt < 4; kt++) {
#pragma unroll
        for (int i = 0; i < 4; i++) {
            int idx = tid + i * 256;
            int row = idx & 127;
            int kq  = (idx >> 7) << 2;
            float4 v = *(const float4*)(W + (m0 + row) * 128 + kt * 32 + kq);
            sW[kq][row] = v.x; sW[kq + 1][row] = v.y;
            sW[kq + 2][row] = v.z; sW[kq + 3][row] = v.w;
        }
#pragma unroll
        for (int i = 0; i < 2; i++) {
            int idx = tid + i * 256;
            int k = idx >> 4, j = (idx & 15) << 2;
            *(float4*)&sX[k][j] = *(const float4*)(X + (kt * 32 + k) * cols + c0 + j);
        }
        __syncthreads();
#pragma unroll
        for (int k = 0; k < 32; k++) {
            ulonglong2 aA = *(const ulonglong2*)&sW[k][ty * 8];
            ulonglong2 aB = *(const ulonglong2*)&sW[k][ty * 8 + 4];
            float4 bq = *(const float4*)&sX[k][tx << 2];
            unsigned long long b0 = pack2(bq.x, bq.x);
            unsigned long long b1 = pack2(bq.y, bq.y);
            unsigned long long b2 = pack2(bq.z, bq.z);
            unsigned long long b3 = pack2(bq.w, bq.w);
            ffma2(acc[0][0], aA.x, b0); ffma2(acc[0][1], aA.x, b1);
            ffma2(acc[0][2], aA.x, b2); ffma2(acc[0][3], aA.x, b3);
            ffma2(acc[1][0], aA.y, b0); ffma2(acc[1][1], aA.y, b1);
            ffma2(acc[1][2], aA.y, b2); ffma2(acc[1][3], aA.y, b3);
            ffma2(acc[2][0], aB.x, b0); ffma2(acc[2][1], aB.x, b1);
            ffma2(acc[2][2], aB.x, b2); ffma2(acc[2][3], aB.x, b3);
            ffma2(acc[3][0], aB.y, b0); ffma2(acc[3][1], aB.y, b1);
            ffma2(acc[3][2], aB.y, b2); ffma2(acc[3][3], aB.y, b3);
        }
        __syncthreads();
    }
#pragma unroll
    for (int r = 0; r < 8; r++) {
        int row = m0 + ty * 8 + r;
        float bs = (bias ? bias[row] : 0.f) + (bias2 ? bias2[row] : 0.f);
        int p = r >> 1;
        float4 o;
        if (r & 1) {
            o.x = unpack2(acc[p][0]).y + bs; o.y = unpack2(acc[p][1]).y + bs;
            o.z = unpack2(acc[p][2]).y + bs; o.w = unpack2(acc[p][3]).y + bs;
        } else {
            o.x = unpack2(acc[p][0]).x + bs; o.y = unpack2(acc[p][1]).x + bs;
            o.z = unpack2(acc[p][2]).x + bs; o.w = unpack2(acc[p][3]).x + bs;
        }
        *(float4*)(Y + row * cols + c0 + (tx << 2)) = o;
    }
}

// ------------ last-layer message aggregation ------------
__global__ void __launch_bounds__(256) msg3_k()
{
    __shared__ float snh[32][24];
    __shared__ float sg[576];
    int f = blockIdx.x >> 2, dg = blockIdx.x & 3;
    int tid = threadIdx.x;
    for (int i = tid; i < 768; i += 256) {
        int d = i / 24, w = i - d * 24;
        snh[d][w] = g_nh[(dg * 32 + d) * NCOLS + f * 24 + w];
    }
    for (int i = tid; i < 576; i += 256) sg[i] = g_gate[f * 576 + i];
    __syncthreads();

    int wl = tid & 31, wp = tid >> 5;
    bool ok = wl < 24;
    for (int p = wp; p < 768; p += 8) {
        int dl = p / 24, v = p - dl * 24;
        int d = dg * 32 + dl;
        float s = 0.f;
        if (ok) s = sg[v * 24 + wl] * fmaxf(snh[dl][wl] + g_epre[(size_t)d * ECOLS + f * 576 + v * 24 + wl], 0.f);
#pragma unroll
        for (int o = 16; o; o >>= 1) s += __shfl_xor_sync(0xffffffffu, s, o);
        if (wl == 0) g_mv[d * NCOLS + f * 24 + v] = s;
    }
}

// ------------ GRU elementwise ------------
__global__ void __launch_bounds__(256) gru_k(const int* __restrict__ nnum)
{
    int idx = blockIdx.x * 256 + threadIdx.x;        // < 128*NCOLS
    int j = idx / NCOLS; int col = idx - j * NCOLS;
    float gir = g_gi[j * NCOLS + col];
    float giz = g_gi[(128 + j) * NCOLS + col];
    float gin = g_gi[(256 + j) * NCOLS + col];
    float ghr = g_gh[j * NCOLS + col];
    float ghz = g_gh[(128 + j) * NCOLS + col];
    float ghn = g_gh[(256 + j) * NCOLS + col];
    float r = sigm(gir + ghr);
    float z = sigm(giz + ghz);
    float n2 = tanhf(gin + r * ghn);
    float h = g_hnode[idx];
    float hn = (1.f - z) * n2 + z * h;
    int f = col / 24; int n = col - f * 24;
    g_hnode[idx] = (n < nnum[f]) ? hn : g_node0[idx];
}

// ------------ persistent LSTM ------------
__device__ __forceinline__ void group_barrier(int b, unsigned want)
{
    __threadfence();
    __syncthreads();
    if (threadIdx.x == 0) {
        unsigned tk = atomicAdd(&g_cnt2[b], 1u);
        if (tk == 15u) {
            g_cnt2[b] = 0;
            __threadfence();
            atomicExch(&g_sense2[b], want);
        } else {
            unsigned v;
            do {
                asm volatile("ld.acquire.gpu.u32 %0, [%1];" : "=r"(v) : "l"(&g_sense2[b]));
            } while (v != want);
        }
    }
    __syncthreads();
}

__global__ void __launch_bounds__(192) lstm_all_k(const float* __restrict__ Whh)
{
    __shared__ __align__(16) float sWt[128][36];
    __shared__ float sH[128][25];
    __shared__ float sG[32][25];
    int tid = threadIdx.x;
    int rg = blockIdx.x & 15, b = blockIdx.x >> 4;

    for (int i = tid; i < 4096; i += 192) {
        int r = i >> 7, k = i & 127;
        int jg = (r >> 3) * 128 + rg * 8 + (r & 7);
        sWt[k][r] = Whh[jg * 128 + k];
    }
    int tr = tid & 7, tc = tid >> 3;
    int hh = tid / 24, nn = tid - hh * 24;
    int jrow = rg * 8 + hh;
    int scol = b * 24 + nn;
    float creg = 0.f;
    unsigned phase = 0;

    for (int t = 0; t < 32; t++) {
        if (t == 0) {
            for (int i = tid; i < 3200; i += 192) (&sH[0][0])[i] = 0.f;
            __syncthreads();
        } else {
            phase++;
            group_barrier(b, phase & 1u);
            const float* hb = g_h + ((t + 1) & 1) * 24576;
            for (int i = tid; i < 3072; i += 192) {
                int j = i / 24, n2 = i - j * 24;
                sH[j][n2] = __ldcg(hb + j * 192 + b * 24 + n2);
            }
            __syncthreads();
        }

        unsigned long long acc0 = 0ull, acc1 = 0ull;
#pragma unroll 8
        for (int k = 0; k < 128; k++) {
            ulonglong2 av = *(const ulonglong2*)&sWt[k][tr * 4];
            float bv = sH[k][tc];
            unsigned long long bs = pack2(bv, bv);
            ffma2(acc0, av.x, bs);
            ffma2(acc1, av.y, bs);
        }
        float2 u0 = unpack2(acc0), u1 = unpack2(acc1);
        sG[tr * 4 + 0][tc] = u0.x; sG[tr * 4 + 1][tc] = u0.y;
        sG[tr * 4 + 2][tc] = u1.x; sG[tr * 4 + 3][tc] = u1.y;
        __syncthreads();

        int colx = (b * 32 + t) * 24 + nn;
        float ig = sG[hh][nn]      + g_xg[(      jrow) * NCOLS + colx];
        float fg = sG[8 + hh][nn]  + g_xg[(128 + jrow) * NCOLS + colx];
        float gg = sG[16 + hh][nn] + g_xg[(256 + jrow) * NCOLS + colx];
        float og = sG[24 + hh][nn] + g_xg[(384 + jrow) * NCOLS + colx];
        creg = sigm(fg) * creg + sigm(ig) * tanhf(gg);
        float hnew = sigm(og) * tanhf(creg);
        __stcg(g_h + (t & 1) * 24576 + jrow * 192 + scol, hnew);
        g_hist[jrow * 6144 + t * 192 + scol] = hnew;
        __syncthreads();
    }
    phase++;
    group_barrier(b, phase & 1u);
}

// ------------ readout ------------
__global__ void __launch_bounds__(256) readout_k(const float* __restrict__ roW,
                                                 const float* __restrict__ rob,
                                                 const int* __restrict__ nnum,
                                                 float* __restrict__ out)
{
    __shared__ float sH[128][65];
    __shared__ float sRo[6][128];
    __shared__ float sRob[6];
    int tid = threadIdx.x;
    int c0 = blockIdx.x * 64;
    for (int i = tid; i < 8192; i += 256) {
        int j = i >> 6, cc = i & 63;
        sH[j][cc] = g_hist[j * 6144 + c0 + cc];
    }
    for (int i = tid; i < 768; i += 256) sRo[i >> 7][i & 127] = roW[i];
    if (tid < 6) sRob[tid] = rob[tid];
    __syncthreads();
    for (int e = tid; e < 384; e += 256) {
        int cc = e / 6, c = e - cc * 6;
        float s = 0.f;
#pragma unroll 8
        for (int j = 0; j < 128; j++) s += sRo[c][j] * sH[j][cc];
        int ct = c0 + cc;
        int t = ct / 192; int srem = ct - t * 192;
        int b = srem / 24; int n = srem - b * 24;
        int f = b * 32 + t;
        out[(f * 24 + n) * 6 + c] = (n < nnum[f]) ? (s + sRob[c]) : 0.f;
    }
}

// ------------ host launcher ------------
extern "C" void kernel_launch(void* const* d_in, const int* in_sizes, int n_in,
                              void* d_out, int out_size)
{
    const float* node     = (const float*)d_in[0];
    const float* edge     = (const float*)d_in[1];
    const float* link_W1  = (const float*)d_in[2];
    const float* link_b1  = (const float*)d_in[3];
    const float* link_W2  = (const float*)d_in[4];
    const float* link_b2  = (const float*)d_in[5];
    const float* msg_Wh   = (const float*)d_in[6];
    const float* msg_We   = (const float*)d_in[7];
    const float* msg_b    = (const float*)d_in[8];
    const float* gru_Wih  = (const float*)d_in[9];
    const float* gru_Whh  = (const float*)d_in[10];
    const float* gru_bih  = (const float*)d_in[11];
    const float* gru_bhh  = (const float*)d_in[12];
    const float* lstm_Wih = (const float*)d_in[13];
    const float* lstm_Whh = (const float*)d_in[14];
    const float* lstm_bih = (const float*)d_in[15];
    const float* lstm_bhh = (const float*)d_in[16];
    const float* ro_W     = (const float*)d_in[17];
    const float* ro_b     = (const float*)d_in[18];
    const int*   nnum     = (const int*)d_in[19];
    float* out = (float*)d_out;

    float* hnode; cudaGetSymbolAddress((void**)&hnode, g_hnode);
    float* nh;    cudaGetSymbolAddress((void**)&nh,    g_nh);
    float* mv;    cudaGetSymbolAddress((void**)&mv,    g_mv);
    float* gi;    cudaGetSymbolAddress((void**)&gi,    g_gi);
    float* gh;    cudaGetSymbolAddress((void**)&gh,    g_gh);
    float* xg;    cudaGetSymbolAddress((void**)&xg,    g_xg);
    unsigned* wA; cudaGetSymbolAddress((void**)&wA,    g_wA);

    static int smem_set = 0;
    if (!smem_set) {
        cudaFuncSetAttribute(edge0_k, cudaFuncAttributeMaxDynamicSharedMemorySize, SM_BYTES);
        cudaFuncSetAttribute(recon_k, cudaFuncAttributeMaxDynamicSharedMemorySize, SM_BYTES);
        smem_set = 1;
    }

    tr_node_k<<<(128 * NCOLS / 4) / 256, 256>>>(node);
    prep_w_k<<<24, 256>>>(link_W1, wA);
    prep_w_k<<<24, 256>>>(msg_We, wA + 24576);

    const int NTILE = ECOLS / 96;   // 1536

    // layer 0: gate0 + epre in one fused tensor-core kernel
    edge0_k<<<NTILE, 256, SM_BYTES>>>(edge, link_b1, link_W2, link_b2, msg_b, nnum);

    for (int p = 0; p < 3; p++) {
        sgemm2_k<<<dim3(NCOLS / 64, 1), 256>>>(msg_Wh, hnode, nullptr, nullptr, nh, NCOLS);
        if (p < 2) {
            recon_k<<<NTILE, 256, SM_BYTES>>>(link_b1, link_W2, link_b2, nnum);
        } else {
            msg3_k<<<1024, 256>>>();
        }
        sgemm2_k<<<dim3(NCOLS / 64, 3), 256>>>(gru_Wih, mv,    gru_bih, nullptr, gi, NCOLS);
        sgemm2_k<<<dim3(NCOLS / 64, 3), 256>>>(gru_Whh, hnode, gru_bhh, nullptr, gh, NCOLS);
        gru_k<<<(128 * NCOLS) / 256, 256>>>(nnum);
    }

    sgemm2_k<<<dim3(NCOLS / 64, 4), 256>>>(lstm_Wih, hnode, lstm_bih, lstm_bhh, xg, NCOLS);
    lstm_all_k<<<128, 192>>>(lstm_Whh);
    readout_k<<<96, 256>>>(ro_W, ro_b, nnum, out);
    (void)in_sizes; (void)n_in; (void)out_size;
}

// round 6
// speedup vs baseline: 1.9438x; 1.0271x over previous
#include <cuda_runtime.h>
#include <cuda_bf16.h>
#include <math.h>
#include <stdint.h>

// ------------ problem constants ------------
#define NFRM   256                  // B*T
#define ECOLS  147456               // NFRM * 576 edge columns
#define NCOLS  6144                 // NFRM * 24 node columns

// ------------ device scratch ------------
__device__ float g_epre  [128 * ECOLS];   // msg_We @ edge + msg_b (loop-invariant)
__device__ float g_gate  [ECOLS];
__device__ float g_node0 [128 * NCOLS];   // transposed node_resnet
__device__ float g_hnode [128 * NCOLS];
__device__ float g_nh    [128 * NCOLS];   // msg_Wh @ h_node
__device__ float g_mv    [128 * NCOLS];
__device__ float g_gi    [384 * NCOLS];
__device__ float g_gh    [384 * NCOLS];
__device__ float g_xg    [512 * NCOLS];   // lstm_Wih @ h_node + bih + bhh
__device__ float g_h     [2 * 128 * 192]; // double-buffered LSTM hidden
__device__ float g_hist  [128 * 6144];    // h history [j][t*192 + b*24 + n]
__device__ unsigned g_cnt2[8];
__device__ unsigned g_sense2[8];
// HMMA A fragments (uint4 each = 4 regs of one lane of one k16-step of one m16 block)
// per m16 block: 24 kk * 32 lanes = 768 uint4
// offsets (uint4): link_W1=0, msg_We=6144, msg_Wh=12288, gru_Wih=18432,
//                  gru_Whh=36864, lstm_Wih=55296  (total 79872)
__device__ uint4 g_wA4[79872];

__device__ __forceinline__ float sigm(float x) { return 1.f / (1.f + expf(-x)); }

__device__ __forceinline__ void ffma2(unsigned long long& acc,
                                      unsigned long long a, unsigned long long b) {
    asm("fma.rn.f32x2 %0, %1, %2, %0;" : "+l"(acc) : "l"(a), "l"(b));
}
__device__ __forceinline__ unsigned long long pack2(float x, float y) {
    unsigned long long r;
    asm("mov.b64 %0, {%1, %2};" : "=l"(r) : "f"(x), "f"(y));
    return r;
}
__device__ __forceinline__ float2 unpack2(unsigned long long v) {
    float2 f;
    asm("mov.b64 {%0, %1}, %2;" : "=f"(f.x), "=f"(f.y) : "l"(v));
    return f;
}
__device__ __forceinline__ void split_bf(float x, __nv_bfloat16& h, __nv_bfloat16& l) {
    h = __float2bfloat16(x);
    l = __float2bfloat16(x - __bfloat162float(h));
}
__device__ __forceinline__ uint32_t smem_to_u32(const void* p) {
    uint32_t a;
    asm("{ .reg .u64 t; cvta.to.shared.u64 t, %1; cvt.u32.u64 %0, t; }" : "=r"(a) : "l"(p));
    return a;
}

// ---- HMMA m16n8k16 bf16 ----
__device__ __forceinline__ void mma_bf16(float* c, uint32_t a0, uint32_t a1,
                                         uint32_t a2, uint32_t a3,
                                         uint32_t b0, uint32_t b1) {
    asm volatile(
        "mma.sync.aligned.m16n8k16.row.col.f32.bf16.bf16.f32 "
        "{%0,%1,%2,%3}, {%4,%5,%6,%7}, {%8,%9}, {%0,%1,%2,%3};"
        : "+f"(c[0]), "+f"(c[1]), "+f"(c[2]), "+f"(c[3])
        : "r"(a0), "r"(a1), "r"(a2), "r"(a3), "r"(b0), "r"(b1));
}

// B tile: bf16 [96 rows(n)][264 cols(k: 0-127 hi, 128-255 lo, 8 pad)]
// row pitch 528 B = 132 words; 132 mod 32 = 4 -> ldmatrix conflict-free.
#define BPITCH_E  264
#define BPITCH_B  528
#define SB_SIZE   50688     // 96*528
#define SNH_OFF   50688     // float[128*24]
#define SG_OFF    62976     // float[96]
#define SRED_OFF  63360     // float[8][104]
#define SM_EDGE   66688
#define SM_HG     50688

// ------------ prep: pack split-bf16 W (K-stacked [Whi|Whi|Wlo]) into HMMA A-frag layout ------------
__global__ void __launch_bounds__(256) prep_w_k(const float* __restrict__ W, uint4* __restrict__ out)
{
    int gidx = blockIdx.x * 256 + threadIdx.x;       // < M16*768
    int mblk = gidx / 768;
    int rem  = gidx - mblk * 768;
    int kk   = rem >> 5;
    int lane = rem & 31;
    int g = lane >> 2, t = lane & 3;

    unsigned regs[4];
#pragma unroll
    for (int r = 0; r < 4; r++) {
        int row = mblk * 16 + g + ((r & 1) ? 8 : 0);
        int k0  = kk * 16 + t * 2 + ((r & 2) ? 8 : 0);
        unsigned pk = 0;
#pragma unroll
        for (int e = 0; e < 2; e++) {
            int ks = k0 + e;
            int region = ks >> 7;            // 0,1 -> hi ; 2 -> lo
            int kloc = ks & 127;
            float w = W[row * 128 + kloc];
            __nv_bfloat16 h, l; split_bf(w, h, l);
            __nv_bfloat16 b = (region < 2) ? h : l;
            pk |= (unsigned)__bfloat16_as_ushort(b) << (e * 16);
        }
        regs[r] = pk;
    }
    out[gidx] = make_uint4(regs[0], regs[1], regs[2], regs[3]);
}

// ------------ warp GEMM pass: C[12][4] = A(m16) @ B(smem 96x[hi|lo]) over 24 k16-steps ------------
// A4 points at this warp's m16 block (768 uint4). B k-steps 16-23 alias back to hi region.
__device__ __forceinline__ void gemm_pass(float c[12][4], const uint4* __restrict__ A4,
                                          uint32_t sbAddr, int lane)
{
    int midx = lane >> 3, row = lane & 7;
    uint32_t base0 = sbAddr + (uint32_t)((((midx >> 1) << 3) + row) * BPITCH_B + (midx & 1) * 16);
#pragma unroll
    for (int nt = 0; nt < 12; nt++)
#pragma unroll
        for (int r = 0; r < 4; r++) c[nt][r] = 0.f;

#pragma unroll 2
    for (int kk = 0; kk < 24; kk++) {
        uint4 a = A4[kk * 32 + lane];
        uint32_t kb = (uint32_t)((kk < 16 ? kk : kk - 16) * 32);
#pragma unroll
        for (int j = 0; j < 6; j++) {
            uint32_t r0, r1, r2, r3;
            asm volatile("ldmatrix.sync.aligned.m8n8.x4.shared.b16 {%0,%1,%2,%3}, [%4];"
                         : "=r"(r0), "=r"(r1), "=r"(r2), "=r"(r3)
                         : "r"(base0 + (uint32_t)(j * 16 * BPITCH_B) + kb));
            mma_bf16(c[2 * j],     a.x, a.y, a.z, a.w, r0, r1);
            mma_bf16(c[2 * j + 1], a.x, a.y, a.z, a.w, r2, r3);
        }
    }
}

// ------------ gate epilogue ------------
__device__ __forceinline__ void gate_epi(float c[12][4], char* smem,
                                         const float* __restrict__ lb1,
                                         const float* __restrict__ W2,
                                         const float* __restrict__ b2p,
                                         const int* __restrict__ nnum,
                                         int c0, int f, int off)
{
    int tid = threadIdx.x;
    int mblk = tid >> 5, lane = tid & 31;
    int g = lane >> 2, t = lane & 3;
    int r0 = mblk * 16 + g;
    float bb0 = lb1[r0], bb8 = lb1[r0 + 8];
    float w0 = W2[r0], w8 = W2[r0 + 8];
    float* sRed = (float*)(smem + SRED_OFF);

    float p0[12], p1[12];
#pragma unroll
    for (int nt = 0; nt < 12; nt++) {
        p0[nt] = fmaxf(c[nt][0] + bb0, 0.f) * w0 + fmaxf(c[nt][2] + bb8, 0.f) * w8;
        p1[nt] = fmaxf(c[nt][1] + bb0, 0.f) * w0 + fmaxf(c[nt][3] + bb8, 0.f) * w8;
    }
#pragma unroll
    for (int nt = 0; nt < 12; nt++) {
#pragma unroll
        for (int m = 4; m <= 16; m <<= 1) {
            p0[nt] += __shfl_xor_sync(0xffffffffu, p0[nt], m);
            p1[nt] += __shfl_xor_sync(0xffffffffu, p1[nt], m);
        }
    }
    if (g == 0) {
#pragma unroll
        for (int nt = 0; nt < 12; nt++) {
            sRed[mblk * 104 + nt * 8 + t * 2]     = p0[nt];
            sRed[mblk * 104 + nt * 8 + t * 2 + 1] = p1[nt];
        }
    }
    __syncthreads();
    if (tid < 96) {
        float s = 0.f;
#pragma unroll
        for (int w = 0; w < 8; w++) s += sRed[w * 104 + tid];
        int v = (off + tid) / 24, ww = (off + tid) - v * 24;
        int cnt = nnum[f];
        g_gate[c0 + tid] = (v < cnt && ww < cnt) ? sigm(s + b2p[0]) : 0.f;
    }
}

// ------------ edge0_k: layer-0 gate + epre (two GEMM passes share one B tile) ------------
__global__ void __launch_bounds__(256, 3) edge0_k(const float* __restrict__ edge,
                                                  const float* __restrict__ lb1,
                                                  const float* __restrict__ W2,
                                                  const float* __restrict__ b2p,
                                                  const float* __restrict__ msg_b,
                                                  const int* __restrict__ nnum)
{
    extern __shared__ char smem[];
    uint32_t sbAddr = smem_to_u32(smem);
    __nv_bfloat16* sBh = (__nv_bfloat16*)smem;
    int tid = threadIdx.x;
    int c0 = blockIdx.x * 96;
    int f = c0 / 576;
    int off = c0 - f * 576;

    // B conversion from original edge layout: rows d = k, cols n
    {
        int d = tid & 127, half = tid >> 7;
        const float* src = edge + (size_t)f * 73728 + d * 576 + off + half * 48;
        for (int i = 0; i < 48; i += 4) {
            float4 x = *(const float4*)(src + i);
            float xs[4] = {x.x, x.y, x.z, x.w};
#pragma unroll
            for (int j = 0; j < 4; j++) {
                int n = half * 48 + i + j;
                __nv_bfloat16 h, l; split_bf(xs[j], h, l);
                sBh[n * BPITCH_E + d]       = h;
                sBh[n * BPITCH_E + 128 + d] = l;
            }
        }
    }
    __syncthreads();

    int mblk = tid >> 5, lane = tid & 31;
    int g = lane >> 2, t = lane & 3;
    float c[12][4];

    // pass 1: link_W1 -> gate0
    gemm_pass(c, g_wA4 + mblk * 768, sbAddr, lane);
    gate_epi(c, smem, lb1, W2, b2p, nnum, c0, f, off);
    __syncthreads();

    // pass 2: msg_We -> epre
    gemm_pass(c, g_wA4 + 6144 + mblk * 768, sbAddr, lane);
    {
        int r0 = mblk * 16 + g;
        float mb0 = msg_b[r0], mb8 = msg_b[r0 + 8];
#pragma unroll
        for (int nt = 0; nt < 12; nt++) {
            int col = c0 + nt * 8 + t * 2;
            *(float2*)(g_epre + (size_t)r0 * ECOLS + col) =
                make_float2(c[nt][0] + mb0, c[nt][1] + mb0);
            *(float2*)(g_epre + (size_t)(r0 + 8) * ECOLS + col) =
                make_float2(c[nt][2] + mb8, c[nt][3] + mb8);
        }
    }
}

// ------------ recon_k: layer p>=1 gate + m_v of layer p-1 (byproduct) ------------
__global__ void __launch_bounds__(256, 3) recon_k(const float* __restrict__ lb1,
                                                  const float* __restrict__ W2,
                                                  const float* __restrict__ b2p,
                                                  const int* __restrict__ nnum)
{
    extern __shared__ char smem[];
    uint32_t sbAddr = smem_to_u32(smem);
    __nv_bfloat16* sBh = (__nv_bfloat16*)smem;
    float* snh = (float*)(smem + SNH_OFF);   // [128][24]
    float* sg  = (float*)(smem + SG_OFF);    // [96]
    int tid = threadIdx.x;
    int c0 = blockIdx.x * 96;
    int f = c0 / 576;
    int off = c0 - f * 576;

    for (int i = tid; i < 3072; i += 256) {
        int d = i / 24, w = i - d * 24;
        snh[d * 24 + w] = g_nh[d * NCOLS + f * 24 + w];
    }
    if (tid < 96) sg[tid] = g_gate[c0 + tid];
    __syncthreads();

    // B conversion from reconstruction h_edge = gate * relu(nh + epre); m_v byproduct
    {
        int d = tid & 127, half = tid >> 7;
        const float* esrc = g_epre + (size_t)d * ECOLS + c0 + half * 48;
        float s0 = 0.f, s1 = 0.f;
        for (int i = 0; i < 48; i += 4) {
            float4 x = *(const float4*)(esrc + i);
            float xs[4] = {x.x, x.y, x.z, x.w};
#pragma unroll
            for (int j = 0; j < 4; j++) {
                int n = half * 48 + i + j;
                int w = n % 24;
                float val = sg[n] * fmaxf(snh[d * 24 + w] + xs[j], 0.f);
                if (i + j < 24) s0 += val; else s1 += val;
                __nv_bfloat16 h, l; split_bf(val, h, l);
                sBh[n * BPITCH_E + d]       = h;
                sBh[n * BPITCH_E + 128 + d] = l;
            }
        }
        int vb = off / 24 + half * 2;
        g_mv[d * NCOLS + f * 24 + vb]     = s0;
        g_mv[d * NCOLS + f * 24 + vb + 1] = s1;
    }
    __syncthreads();

    int mblk = tid >> 5, lane = tid & 31;
    float c[12][4];
    gemm_pass(c, g_wA4 + mblk * 768, sbAddr, lane);
    gate_epi(c, smem, lb1, W2, b2p, nnum, c0, f, off);
}

// ------------ generic HMMA GEMM: Y[M,cols] = W @ X[128,cols] (+bias+bias2) ------------
// grid (cols/96, M/128); Afrag pre-packed; X converted to split-bf16 in-kernel.
__global__ void __launch_bounds__(256, 3) hgemm_k(const uint4* __restrict__ Afrag,
                                                  const float* __restrict__ X,
                                                  const float* __restrict__ bias,
                                                  const float* __restrict__ bias2,
                                                  float* __restrict__ Y, int cols)
{
    extern __shared__ char smem[];
    uint32_t sbAddr = smem_to_u32(smem);
    __nv_bfloat16* sBh = (__nv_bfloat16*)smem;
    int tid = threadIdx.x;
    int c0 = blockIdx.x * 96;

    {
        int d = tid & 127, half = tid >> 7;
        const float* src = X + (size_t)d * cols + c0 + half * 48;
        for (int i = 0; i < 48; i += 4) {
            float4 x = *(const float4*)(src + i);
            float xs[4] = {x.x, x.y, x.z, x.w};
#pragma unroll
            for (int j = 0; j < 4; j++) {
                int n = half * 48 + i + j;
                __nv_bfloat16 h, l; split_bf(xs[j], h, l);
                sBh[n * BPITCH_E + d]       = h;
                sBh[n * BPITCH_E + 128 + d] = l;
            }
        }
    }
    __syncthreads();

    int mblk = tid >> 5, lane = tid & 31;
    int g = lane >> 2, t = lane & 3;
    float c[12][4];
    gemm_pass(c, Afrag + (blockIdx.y * 8 + mblk) * 768, sbAddr, lane);

    int r0 = blockIdx.y * 128 + mblk * 16 + g;
    float b0v = (bias ? bias[r0] : 0.f) + (bias2 ? bias2[r0] : 0.f);
    float b8v = (bias ? bias[r0 + 8] : 0.f) + (bias2 ? bias2[r0 + 8] : 0.f);
#pragma unroll
    for (int nt = 0; nt < 12; nt++) {
        int col = c0 + nt * 8 + t * 2;
        *(float2*)(Y + (size_t)r0 * cols + col) =
            make_float2(c[nt][0] + b0v, c[nt][1] + b0v);
        *(float2*)(Y + (size_t)(r0 + 8) * cols + col) =
            make_float2(c[nt][2] + b8v, c[nt][3] + b8v);
    }
}

// ------------ node transpose ------------
__global__ void __launch_bounds__(256) tr_node_k(const float* __restrict__ in)
{
    int o4 = blockIdx.x * 256 + threadIdx.x;         // < 128*NCOLS/4
    int d = o4 / 1536; int c4 = o4 - d * 1536;
    int f = c4 / 6;    int n4 = c4 - f * 6;
    float4 v = *(const float4*)(in + f * 3072 + d * 24 + n4 * 4);
    int dst = d * NCOLS + f * 24 + n4 * 4;
    *(float4*)(g_node0 + dst) = v;
    *(float4*)(g_hnode + dst) = v;
}

// ------------ last-layer message aggregation ------------
__global__ void __launch_bounds__(256) msg3_k()
{
    __shared__ float snh[32][24];
    __shared__ float sg[576];
    int f = blockIdx.x >> 2, dg = blockIdx.x & 3;
    int tid = threadIdx.x;
    for (int i = tid; i < 768; i += 256) {
        int d = i / 24, w = i - d * 24;
        snh[d][w] = g_nh[(dg * 32 + d) * NCOLS + f * 24 + w];
    }
    for (int i = tid; i < 576; i += 256) sg[i] = g_gate[f * 576 + i];
    __syncthreads();

    int wl = tid & 31, wp = tid >> 5;
    bool ok = wl < 24;
    for (int p = wp; p < 768; p += 8) {
        int dl = p / 24, v = p - dl * 24;
        int d = dg * 32 + dl;
        float s = 0.f;
        if (ok) s = sg[v * 24 + wl] * fmaxf(snh[dl][wl] + g_epre[(size_t)d * ECOLS + f * 576 + v * 24 + wl], 0.f);
#pragma unroll
        for (int o = 16; o; o >>= 1) s += __shfl_xor_sync(0xffffffffu, s, o);
        if (wl == 0) g_mv[d * NCOLS + f * 24 + v] = s;
    }
}

// ------------ GRU elementwise ------------
__global__ void __launch_bounds__(256) gru_k(const int* __restrict__ nnum)
{
    int idx = blockIdx.x * 256 + threadIdx.x;        // < 128*NCOLS
    int j = idx / NCOLS; int col = idx - j * NCOLS;
    float gir = g_gi[j * NCOLS + col];
    float giz = g_gi[(128 + j) * NCOLS + col];
    float gin = g_gi[(256 + j) * NCOLS + col];
    float ghr = g_gh[j * NCOLS + col];
    float ghz = g_gh[(128 + j) * NCOLS + col];
    float ghn = g_gh[(256 + j) * NCOLS + col];
    float r = sigm(gir + ghr);
    float z = sigm(giz + ghz);
    float n2 = tanhf(gin + r * ghn);
    float h = g_hnode[idx];
    float hn = (1.f - z) * n2 + z * h;
    int f = col / 24; int n = col - f * 24;
    g_hnode[idx] = (n < nnum[f]) ? hn : g_node0[idx];
}

// ------------ persistent LSTM ------------
__device__ __forceinline__ void group_barrier(int b, unsigned want)
{
    __threadfence();
    __syncthreads();
    if (threadIdx.x == 0) {
        unsigned tk = atomicAdd(&g_cnt2[b], 1u);
        if (tk == 15u) {
            g_cnt2[b] = 0;
            __threadfence();
            atomicExch(&g_sense2[b], want);
        } else {
            unsigned v;
            do {
                asm volatile("ld.acquire.gpu.u32 %0, [%1];" : "=r"(v) : "l"(&g_sense2[b]));
            } while (v != want);
        }
    }
    __syncthreads();
}

__global__ void __launch_bounds__(192) lstm_all_k(const float* __restrict__ Whh)
{
    __shared__ __align__(16) float sWt[128][36];
    __shared__ float sH[128][25];
    __shared__ float sG[32][25];
    int tid = threadIdx.x;
    int rg = blockIdx.x & 15, b = blockIdx.x >> 4;

    for (int i = tid; i < 4096; i += 192) {
        int r = i >> 7, k = i & 127;
        int jg = (r >> 3) * 128 + rg * 8 + (r & 7);
        sWt[k][r] = Whh[jg * 128 + k];
    }
    int tr = tid & 7, tc = tid >> 3;
    int hh = tid / 24, nn = tid - hh * 24;
    int jrow = rg * 8 + hh;
    int scol = b * 24 + nn;
    float creg = 0.f;
    unsigned phase = 0;

    for (int t = 0; t < 32; t++) {
        if (t == 0) {
            for (int i = tid; i < 3200; i += 192) (&sH[0][0])[i] = 0.f;
            __syncthreads();
        } else {
            phase++;
            group_barrier(b, phase & 1u);
            const float* hb = g_h + ((t + 1) & 1) * 24576;
            for (int i = tid; i < 3072; i += 192) {
                int j = i / 24, n2 = i - j * 24;
                sH[j][n2] = __ldcg(hb + j * 192 + b * 24 + n2);
            }
            __syncthreads();
        }

        unsigned long long acc0 = 0ull, acc1 = 0ull;
#pragma unroll 8
        for (int k = 0; k < 128; k++) {
            ulonglong2 av = *(const ulonglong2*)&sWt[k][tr * 4];
            float bv = sH[k][tc];
            unsigned long long bs = pack2(bv, bv);
            ffma2(acc0, av.x, bs);
            ffma2(acc1, av.y, bs);
        }
        float2 u0 = unpack2(acc0), u1 = unpack2(acc1);
        sG[tr * 4 + 0][tc] = u0.x; sG[tr * 4 + 1][tc] = u0.y;
        sG[tr * 4 + 2][tc] = u1.x; sG[tr * 4 + 3][tc] = u1.y;
        __syncthreads();

        int colx = (b * 32 + t) * 24 + nn;
        float ig = sG[hh][nn]      + g_xg[(      jrow) * NCOLS + colx];
        float fg = sG[8 + hh][nn]  + g_xg[(128 + jrow) * NCOLS + colx];
        float gg = sG[16 + hh][nn] + g_xg[(256 + jrow) * NCOLS + colx];
        float og = sG[24 + hh][nn] + g_xg[(384 + jrow) * NCOLS + colx];
        creg = sigm(fg) * creg + sigm(ig) * tanhf(gg);
        float hnew = sigm(og) * tanhf(creg);
        __stcg(g_h + (t & 1) * 24576 + jrow * 192 + scol, hnew);
        g_hist[jrow * 6144 + t * 192 + scol] = hnew;
        __syncthreads();
    }
    phase++;
    group_barrier(b, phase & 1u);
}

// ------------ readout ------------
__global__ void __launch_bounds__(256) readout_k(const float* __restrict__ roW,
                                                 const float* __restrict__ rob,
                                                 const int* __restrict__ nnum,
                                                 float* __restrict__ out)
{
    __shared__ float sH[128][65];
    __shared__ float sRo[6][128];
    __shared__ float sRob[6];
    int tid = threadIdx.x;
    int c0 = blockIdx.x * 64;
    for (int i = tid; i < 8192; i += 256) {
        int j = i >> 6, cc = i & 63;
        sH[j][cc] = g_hist[j * 6144 + c0 + cc];
    }
    for (int i = tid; i < 768; i += 256) sRo[i >> 7][i & 127] = roW[i];
    if (tid < 6) sRob[tid] = rob[tid];
    __syncthreads();
    for (int e = tid; e < 384; e += 256) {
        int cc = e / 6, c = e - cc * 6;
        float s = 0.f;
#pragma unroll 8
        for (int j = 0; j < 128; j++) s += sRo[c][j] * sH[j][cc];
        int ct = c0 + cc;
        int t = ct / 192; int srem = ct - t * 192;
        int b = srem / 24; int n = srem - b * 24;
        int f = b * 32 + t;
        out[(f * 24 + n) * 6 + c] = (n < nnum[f]) ? (s + sRob[c]) : 0.f;
    }
}

// ------------ host launcher ------------
extern "C" void kernel_launch(void* const* d_in, const int* in_sizes, int n_in,
                              void* d_out, int out_size)
{
    const float* node     = (const float*)d_in[0];
    const float* edge     = (const float*)d_in[1];
    const float* link_W1  = (const float*)d_in[2];
    const float* link_b1  = (const float*)d_in[3];
    const float* link_W2  = (const float*)d_in[4];
    const float* link_b2  = (const float*)d_in[5];
    const float* msg_Wh   = (const float*)d_in[6];
    const float* msg_We   = (const float*)d_in[7];
    const float* msg_b    = (const float*)d_in[8];
    const float* gru_Wih  = (const float*)d_in[9];
    const float* gru_Whh  = (const float*)d_in[10];
    const float* gru_bih  = (const float*)d_in[11];
    const float* gru_bhh  = (const float*)d_in[12];
    const float* lstm_Wih = (const float*)d_in[13];
    const float* lstm_Whh = (const float*)d_in[14];
    const float* lstm_bih = (const float*)d_in[15];
    const float* lstm_bhh = (const float*)d_in[16];
    const float* ro_W     = (const float*)d_in[17];
    const float* ro_b     = (const float*)d_in[18];
    const int*   nnum     = (const int*)d_in[19];
    float* out = (float*)d_out;

    float* hnode; cudaGetSymbolAddress((void**)&hnode, g_hnode);
    float* nh;    cudaGetSymbolAddress((void**)&nh,    g_nh);
    float* mv;    cudaGetSymbolAddress((void**)&mv,    g_mv);
    float* gi;    cudaGetSymbolAddress((void**)&gi,    g_gi);
    float* gh;    cudaGetSymbolAddress((void**)&gh,    g_gh);
    float* xg;    cudaGetSymbolAddress((void**)&xg,    g_xg);
    uint4* wA;    cudaGetSymbolAddress((void**)&wA,    g_wA4);

    static int smem_set = 0;
    if (!smem_set) {
        cudaFuncSetAttribute(edge0_k, cudaFuncAttributeMaxDynamicSharedMemorySize, SM_EDGE);
        cudaFuncSetAttribute(recon_k, cudaFuncAttributeMaxDynamicSharedMemorySize, SM_EDGE);
        cudaFuncSetAttribute(hgemm_k, cudaFuncAttributeMaxDynamicSharedMemorySize, SM_HG);
        smem_set = 1;
    }

    tr_node_k<<<(128 * NCOLS / 4) / 256, 256>>>(node);
    // pack all weight matrices into HMMA fragments
    prep_w_k<<<24, 256>>>(link_W1,  wA);            // 128 rows
    prep_w_k<<<24, 256>>>(msg_We,   wA + 6144);     // 128
    prep_w_k<<<24, 256>>>(msg_Wh,   wA + 12288);    // 128
    prep_w_k<<<72, 256>>>(gru_Wih,  wA + 18432);    // 384
    prep_w_k<<<72, 256>>>(gru_Whh,  wA + 36864);    // 384
    prep_w_k<<<96, 256>>>(lstm_Wih, wA + 55296);    // 512

    const int NTILE = ECOLS / 96;   // 1536
    const int NCT   = NCOLS / 96;   // 64

    // layer 0: gate0 + epre in one fused tensor-core kernel
    edge0_k<<<NTILE, 256, SM_EDGE>>>(edge, link_b1, link_W2, link_b2, msg_b, nnum);

    for (int p = 0; p < 3; p++) {
        hgemm_k<<<dim3(NCT, 1), 256, SM_HG>>>(wA + 12288, hnode, nullptr, nullptr, nh, NCOLS);
        if (p < 2) {
            recon_k<<<NTILE, 256, SM_EDGE>>>(link_b1, link_W2, link_b2, nnum);
        } else {
            msg3_k<<<1024, 256>>>();
        }
        hgemm_k<<<dim3(NCT, 3), 256, SM_HG>>>(wA + 18432, mv,    gru_bih, nullptr, gi, NCOLS);
        hgemm_k<<<dim3(NCT, 3), 256, SM_HG>>>(wA + 36864, hnode, gru_bhh, nullptr, gh, NCOLS);
        gru_k<<<(128 * NCOLS) / 256, 256>>>(nnum);
    }

    hgemm_k<<<dim3(NCT, 4), 256, SM_HG>>>(wA + 55296, hnode, lstm_bih, lstm_bhh, xg, NCOLS);
    lstm_all_k<<<128, 192>>>(lstm_Whh);
    readout_k<<<96, 256>>>(ro_W, ro_b, nnum, out);
    (void)in_sizes; (void)n_in; (void)out_size;
}

// round 7
// speedup vs baseline: 1.9513x; 1.0038x over previous
#include <cuda_runtime.h>
#include <cuda_bf16.h>
#include <math.h>
#include <stdint.h>

// ------------ problem constants ------------
#define NFRM   256                  // B*T
#define ECOLS  147456               // NFRM * 576 edge columns
#define NCOLS  6144                 // NFRM * 24 node columns

// ------------ device scratch ------------
__device__ float g_epre  [128 * ECOLS];   // msg_We @ edge + msg_b (loop-invariant)
__device__ float g_gate  [ECOLS];
__device__ float g_node0 [128 * NCOLS];   // transposed node_resnet
__device__ float g_hnode [128 * NCOLS];
__device__ float g_nh    [128 * NCOLS];   // msg_Wh @ h_node
__device__ float g_mv    [128 * NCOLS];
__device__ float g_gi    [384 * NCOLS];
__device__ float g_gh    [384 * NCOLS];
__device__ float g_xg    [512 * NCOLS];   // lstm_Wih @ h_node + bih + bhh
__device__ float g_h     [2 * 128 * 192]; // double-buffered LSTM hidden
__device__ float g_hist  [128 * 6144];    // h history [j][t*192 + b*24 + n]
__device__ unsigned g_cnt2[8];
__device__ unsigned g_sense2[8];
// HMMA A fragments: per m16 block 768 uint4 (24 kk * 32 lanes)
// offsets (uint4): link_W1=0, msg_We=6144, msg_Wh=12288, gru_Wih=18432,
//                  gru_Whh=36864, lstm_Wih=55296  (total 79872)
__device__ uint4 g_wA4[79872];

__device__ __forceinline__ float sigm(float x) { return 1.f / (1.f + expf(-x)); }

__device__ __forceinline__ void ffma2(unsigned long long& acc,
                                      unsigned long long a, unsigned long long b) {
    asm("fma.rn.f32x2 %0, %1, %2, %0;" : "+l"(acc) : "l"(a), "l"(b));
}
__device__ __forceinline__ unsigned long long pack2(float x, float y) {
    unsigned long long r;
    asm("mov.b64 %0, {%1, %2};" : "=l"(r) : "f"(x), "f"(y));
    return r;
}
__device__ __forceinline__ float2 unpack2(unsigned long long v) {
    float2 f;
    asm("mov.b64 {%0, %1}, %2;" : "=f"(f.x), "=f"(f.y) : "l"(v));
    return f;
}
__device__ __forceinline__ void split_bf(float x, __nv_bfloat16& h, __nv_bfloat16& l) {
    h = __float2bfloat16(x);
    l = __float2bfloat16(x - __bfloat162float(h));
}
// split a d-pair into packed hi-word and lo-word
__device__ __forceinline__ void split_pair(float x0, float x1, unsigned& hw, unsigned& lw) {
    __nv_bfloat16 h0, l0, h1, l1;
    split_bf(x0, h0, l0); split_bf(x1, h1, l1);
    hw = (unsigned)__bfloat16_as_ushort(h0) | ((unsigned)__bfloat16_as_ushort(h1) << 16);
    lw = (unsigned)__bfloat16_as_ushort(l0) | ((unsigned)__bfloat16_as_ushort(l1) << 16);
}
__device__ __forceinline__ uint32_t smem_to_u32(const void* p) {
    uint32_t a;
    asm("{ .reg .u64 t; cvta.to.shared.u64 t, %1; cvt.u32.u64 %0, t; }" : "=r"(a) : "l"(p));
    return a;
}

// ---- HMMA m16n8k16 bf16 ----
__device__ __forceinline__ void mma_bf16(float* c, uint32_t a0, uint32_t a1,
                                         uint32_t a2, uint32_t a3,
                                         uint32_t b0, uint32_t b1) {
    asm volatile(
        "mma.sync.aligned.m16n8k16.row.col.f32.bf16.bf16.f32 "
        "{%0,%1,%2,%3}, {%4,%5,%6,%7}, {%8,%9}, {%0,%1,%2,%3};"
        : "+f"(c[0]), "+f"(c[1]), "+f"(c[2]), "+f"(c[3])
        : "r"(a0), "r"(a1), "r"(a2), "r"(a3), "r"(b0), "r"(b1));
}

// B tile: bf16 [96 rows(n)][264 cols(k: 0-127 hi, 128-255 lo, 8 pad)]
// row pitch 528 B = 132 words; 132 mod 32 = 4 -> ldmatrix conflict-free.
#define BPITCH_W  132       // words per B row
#define BPITCH_B  528
#define SNH_OFF   50688     // float[128*24]
#define SG_OFF    62976     // float[96]
#define SRED_OFF  63360     // float[8][104]
#define SM_EDGE   66688
#define SM_HG     50688

// ------------ prep: pack split-bf16 W (K-stacked [Whi|Whi|Wlo]) into HMMA A-frag layout ------------
__device__ __forceinline__ void prep_one(const float* __restrict__ W, uint4* __restrict__ out,
                                         int gidx)
{
    int mblk = gidx / 768;
    int rem  = gidx - mblk * 768;
    int kk   = rem >> 5;
    int lane = rem & 31;
    int g = lane >> 2, t = lane & 3;
    unsigned regs[4];
#pragma unroll
    for (int r = 0; r < 4; r++) {
        int row = mblk * 16 + g + ((r & 1) ? 8 : 0);
        int k0  = kk * 16 + t * 2 + ((r & 2) ? 8 : 0);
        unsigned pk = 0;
#pragma unroll
        for (int e = 0; e < 2; e++) {
            int ks = k0 + e;
            int region = ks >> 7;
            int kloc = ks & 127;
            float w = W[row * 128 + kloc];
            __nv_bfloat16 h, l; split_bf(w, h, l);
            __nv_bfloat16 b = (region < 2) ? h : l;
            pk |= (unsigned)__bfloat16_as_ushort(b) << (e * 16);
        }
        regs[r] = pk;
    }
    out[gidx] = make_uint4(regs[0], regs[1], regs[2], regs[3]);
}

// blocks 0-23: link_W1; 24-47: msg_We; 48-71: msg_Wh
__global__ void __launch_bounds__(256) prep_a_k(const float* __restrict__ w1,
                                                const float* __restrict__ we,
                                                const float* __restrict__ wh,
                                                uint4* __restrict__ out)
{
    int b = blockIdx.x;
    if (b < 24)      prep_one(w1, out,          b * 256 + threadIdx.x);
    else if (b < 48) prep_one(we, out + 6144,  (b - 24) * 256 + threadIdx.x);
    else             prep_one(wh, out + 12288, (b - 48) * 256 + threadIdx.x);
}
// blocks 0-71: gru_Wih; 72-143: gru_Whh; 144-239: lstm_Wih
__global__ void __launch_bounds__(256) prep_b_k(const float* __restrict__ wih,
                                                const float* __restrict__ whh,
                                                const float* __restrict__ lih,
                                                uint4* __restrict__ out)
{
    int b = blockIdx.x;
    if (b < 72)       prep_one(wih, out + 18432,  b * 256 + threadIdx.x);
    else if (b < 144) prep_one(whh, out + 36864, (b - 72) * 256 + threadIdx.x);
    else              prep_one(lih, out + 55296, (b - 144) * 256 + threadIdx.x);
}

// ------------ warp GEMM pass: C[12][4] = A(m16) @ B(smem 96x[hi|lo]) over 24 k16-steps ------------
__device__ __forceinline__ void gemm_pass(float c[12][4], const uint4* __restrict__ A4,
                                          uint32_t sbAddr, int lane)
{
    int midx = lane >> 3, row = lane & 7;
    uint32_t base0 = sbAddr + (uint32_t)((((midx >> 1) << 3) + row) * BPITCH_B + (midx & 1) * 16);
#pragma unroll
    for (int nt = 0; nt < 12; nt++)
#pragma unroll
        for (int r = 0; r < 4; r++) c[nt][r] = 0.f;

#pragma unroll 2
    for (int kk = 0; kk < 24; kk++) {
        uint4 a = A4[kk * 32 + lane];
        uint32_t kb = (uint32_t)((kk < 16 ? kk : kk - 16) * 32);
#pragma unroll
        for (int j = 0; j < 6; j++) {
            uint32_t r0, r1, r2, r3;
            asm volatile("ldmatrix.sync.aligned.m8n8.x4.shared.b16 {%0,%1,%2,%3}, [%4];"
                         : "=r"(r0), "=r"(r1), "=r"(r2), "=r"(r3)
                         : "r"(base0 + (uint32_t)(j * 16 * BPITCH_B) + kb));
            mma_bf16(c[2 * j],     a.x, a.y, a.z, a.w, r0, r1);
            mma_bf16(c[2 * j + 1], a.x, a.y, a.z, a.w, r2, r3);
        }
    }
}

// ------------ gate epilogue ------------
__device__ __forceinline__ void gate_epi(float c[12][4], char* smem,
                                         const float* __restrict__ lb1,
                                         const float* __restrict__ W2,
                                         const float* __restrict__ b2p,
                                         const int* __restrict__ nnum,
                                         int c0, int f, int off)
{
    int tid = threadIdx.x;
    int mblk = tid >> 5, lane = tid & 31;
    int g = lane >> 2, t = lane & 3;
    int r0 = mblk * 16 + g;
    float bb0 = lb1[r0], bb8 = lb1[r0 + 8];
    float w0 = W2[r0], w8 = W2[r0 + 8];
    float* sRed = (float*)(smem + SRED_OFF);

    float p0[12], p1[12];
#pragma unroll
    for (int nt = 0; nt < 12; nt++) {
        p0[nt] = fmaxf(c[nt][0] + bb0, 0.f) * w0 + fmaxf(c[nt][2] + bb8, 0.f) * w8;
        p1[nt] = fmaxf(c[nt][1] + bb0, 0.f) * w0 + fmaxf(c[nt][3] + bb8, 0.f) * w8;
    }
#pragma unroll
    for (int nt = 0; nt < 12; nt++) {
#pragma unroll
        for (int m = 4; m <= 16; m <<= 1) {
            p0[nt] += __shfl_xor_sync(0xffffffffu, p0[nt], m);
            p1[nt] += __shfl_xor_sync(0xffffffffu, p1[nt], m);
        }
    }
    if (g == 0) {
#pragma unroll
        for (int nt = 0; nt < 12; nt++) {
            sRed[mblk * 104 + nt * 8 + t * 2]     = p0[nt];
            sRed[mblk * 104 + nt * 8 + t * 2 + 1] = p1[nt];
        }
    }
    __syncthreads();
    if (tid < 96) {
        float s = 0.f;
#pragma unroll
        for (int w = 0; w < 8; w++) s += sRed[w * 104 + tid];
        int v = (off + tid) / 24, ww = (off + tid) - v * 24;
        int cnt = nnum[f];
        g_gate[c0 + tid] = (v < cnt && ww < cnt) ? sigm(s + b2p[0]) : 0.f;
    }
}

// ------------ edge0_k: layer-0 gate + epre (two GEMM passes share one B tile) ------------
__global__ void __launch_bounds__(256, 3) edge0_k(const float* __restrict__ edge,
                                                  const float* __restrict__ lb1,
                                                  const float* __restrict__ W2,
                                                  const float* __restrict__ b2p,
                                                  const float* __restrict__ msg_b,
                                                  const int* __restrict__ nnum)
{
    extern __shared__ char smem[];
    uint32_t sbAddr = smem_to_u32(smem);
    unsigned* sBw = (unsigned*)smem;
    int tid = threadIdx.x;
    int c0 = blockIdx.x * 96;
    int f = c0 / 576;
    int off = c0 - f * 576;

    // B conversion, d-pair packed: q = n-quarter, dp = d-pair
    {
        int q = tid >> 6, dp = tid & 63;
        const float* s0 = edge + (size_t)f * 73728 + (2 * dp) * 576 + off + q * 24;
        const float* s1 = s0 + 576;
        for (int i = 0; i < 24; i += 4) {
            float4 x0 = *(const float4*)(s0 + i);
            float4 x1 = *(const float4*)(s1 + i);
            float a0[4] = {x0.x, x0.y, x0.z, x0.w};
            float a1[4] = {x1.x, x1.y, x1.z, x1.w};
#pragma unroll
            for (int j = 0; j < 4; j++) {
                int n = q * 24 + i + j;
                unsigned hw, lw; split_pair(a0[j], a1[j], hw, lw);
                sBw[n * BPITCH_W + dp]      = hw;
                sBw[n * BPITCH_W + 64 + dp] = lw;
            }
        }
    }
    __syncthreads();

    int mblk = tid >> 5, lane = tid & 31;
    int g = lane >> 2, t = lane & 3;
    float c[12][4];

    // pass 1: link_W1 -> gate0
    gemm_pass(c, g_wA4 + mblk * 768, sbAddr, lane);
    gate_epi(c, smem, lb1, W2, b2p, nnum, c0, f, off);
    __syncthreads();

    // pass 2: msg_We -> epre
    gemm_pass(c, g_wA4 + 6144 + mblk * 768, sbAddr, lane);
    {
        int r0 = mblk * 16 + g;
        float mb0 = msg_b[r0], mb8 = msg_b[r0 + 8];
#pragma unroll
        for (int nt = 0; nt < 12; nt++) {
            int col = c0 + nt * 8 + t * 2;
            *(float2*)(g_epre + (size_t)r0 * ECOLS + col) =
                make_float2(c[nt][0] + mb0, c[nt][1] + mb0);
            *(float2*)(g_epre + (size_t)(r0 + 8) * ECOLS + col) =
                make_float2(c[nt][2] + mb8, c[nt][3] + mb8);
        }
    }
}

// ------------ recon_k: layer p>=1 gate + m_v of layer p-1 (byproduct) ------------
__global__ void __launch_bounds__(256, 3) recon_k(const float* __restrict__ lb1,
                                                  const float* __restrict__ W2,
                                                  const float* __restrict__ b2p,
                                                  const int* __restrict__ nnum)
{
    extern __shared__ char smem[];
    uint32_t sbAddr = smem_to_u32(smem);
    unsigned* sBw = (unsigned*)smem;
    float* snh = (float*)(smem + SNH_OFF);   // [128][24]
    float* sg  = (float*)(smem + SG_OFF);    // [96]
    int tid = threadIdx.x;
    int c0 = blockIdx.x * 96;
    int f = c0 / 576;
    int off = c0 - f * 576;

    for (int i = tid; i < 3072; i += 256) {
        int d = i / 24, w = i - d * 24;
        snh[d * 24 + w] = g_nh[d * NCOLS + f * 24 + w];
    }
    if (tid < 96) sg[tid] = g_gate[c0 + tid];
    __syncthreads();

    // B conversion from reconstruction h_edge = gate * relu(nh + epre); m_v byproduct
    {
        int q = tid >> 6, dp = tid & 63;
        int d0 = 2 * dp, d1 = d0 + 1;
        const float* s0 = g_epre + (size_t)d0 * ECOLS + c0 + q * 24;
        const float* s1 = s0 + ECOLS;
        float sum0 = 0.f, sum1 = 0.f;
        for (int i = 0; i < 24; i += 4) {
            float4 x0 = *(const float4*)(s0 + i);
            float4 x1 = *(const float4*)(s1 + i);
            float a0[4] = {x0.x, x0.y, x0.z, x0.w};
            float a1[4] = {x1.x, x1.y, x1.z, x1.w};
#pragma unroll
            for (int j = 0; j < 4; j++) {
                int w = i + j;
                int n = q * 24 + w;
                float gv = sg[n];
                float v0 = gv * fmaxf(snh[d0 * 24 + w] + a0[j], 0.f);
                float v1 = gv * fmaxf(snh[d1 * 24 + w] + a1[j], 0.f);
                sum0 += v0; sum1 += v1;
                unsigned hw, lw; split_pair(v0, v1, hw, lw);
                sBw[n * BPITCH_W + dp]      = hw;
                sBw[n * BPITCH_W + 64 + dp] = lw;
            }
        }
        int v = off / 24 + q;
        g_mv[d0 * NCOLS + f * 24 + v] = sum0;
        g_mv[d1 * NCOLS + f * 24 + v] = sum1;
    }
    __syncthreads();

    int mblk = tid >> 5, lane = tid & 31;
    float c[12][4];
    gemm_pass(c, g_wA4 + mblk * 768, sbAddr, lane);
    gate_epi(c, smem, lb1, W2, b2p, nnum, c0, f, off);
}

// ------------ shared hgemm body ------------
__device__ __forceinline__ void hgemm_body(const uint4* __restrict__ Afrag, int mrowblk,
                                           const float* __restrict__ X,
                                           const float* __restrict__ bias,
                                           const float* __restrict__ bias2,
                                           float* __restrict__ Y, int cols, int c0,
                                           char* smem, uint32_t sbAddr)
{
    unsigned* sBw = (unsigned*)smem;
    int tid = threadIdx.x;
    {
        int q = tid >> 6, dp = tid & 63;
        const float* s0 = X + (size_t)(2 * dp) * cols + c0 + q * 24;
        const float* s1 = s0 + cols;
        for (int i = 0; i < 24; i += 4) {
            float4 x0 = *(const float4*)(s0 + i);
            float4 x1 = *(const float4*)(s1 + i);
            float a0[4] = {x0.x, x0.y, x0.z, x0.w};
            float a1[4] = {x1.x, x1.y, x1.z, x1.w};
#pragma unroll
            for (int j = 0; j < 4; j++) {
                int n = q * 24 + i + j;
                unsigned hw, lw; split_pair(a0[j], a1[j], hw, lw);
                sBw[n * BPITCH_W + dp]      = hw;
                sBw[n * BPITCH_W + 64 + dp] = lw;
            }
        }
    }
    __syncthreads();

    int mblk = tid >> 5, lane = tid & 31;
    int g = lane >> 2, t = lane & 3;
    float c[12][4];
    gemm_pass(c, Afrag + (mrowblk * 8 + mblk) * 768, sbAddr, lane);

    int r0 = mrowblk * 128 + mblk * 16 + g;
    float b0v = (bias ? bias[r0] : 0.f) + (bias2 ? bias2[r0] : 0.f);
    float b8v = (bias ? bias[r0 + 8] : 0.f) + (bias2 ? bias2[r0 + 8] : 0.f);
#pragma unroll
    for (int nt = 0; nt < 12; nt++) {
        int col = c0 + nt * 8 + t * 2;
        *(float2*)(Y + (size_t)r0 * cols + col) =
            make_float2(c[nt][0] + b0v, c[nt][1] + b0v);
        *(float2*)(Y + (size_t)(r0 + 8) * cols + col) =
            make_float2(c[nt][2] + b8v, c[nt][3] + b8v);
    }
}

__global__ void __launch_bounds__(256, 3) hgemm_k(const uint4* __restrict__ Afrag,
                                                  const float* __restrict__ X,
                                                  const float* __restrict__ bias,
                                                  const float* __restrict__ bias2,
                                                  float* __restrict__ Y, int cols)
{
    extern __shared__ char smem[];
    hgemm_body(Afrag, blockIdx.y, X, bias, bias2, Y, cols, blockIdx.x * 96,
               smem, smem_to_u32(smem));
}

// gi and gh in one launch: y<3 -> gi, y>=3 -> gh
__global__ void __launch_bounds__(256, 3) gigh_k(const uint4* __restrict__ wA)
{
    extern __shared__ char smem[];
    int by = blockIdx.y;
    if (by < 3)
        hgemm_body(wA + 18432, by, g_mv, nullptr, nullptr, g_gi, NCOLS,
                   blockIdx.x * 96, smem, smem_to_u32(smem));
    else
        hgemm_body(wA + 36864, by - 3, g_hnode, nullptr, nullptr, g_gh, NCOLS,
                   blockIdx.x * 96, smem, smem_to_u32(smem));
}

// ------------ node transpose ------------
__global__ void __launch_bounds__(256) tr_node_k(const float* __restrict__ in)
{
    int o4 = blockIdx.x * 256 + threadIdx.x;         // < 128*NCOLS/4
    int d = o4 / 1536; int c4 = o4 - d * 1536;
    int f = c4 / 6;    int n4 = c4 - f * 6;
    float4 v = *(const float4*)(in + f * 3072 + d * 24 + n4 * 4);
    int dst = d * NCOLS + f * 24 + n4 * 4;
    *(float4*)(g_node0 + dst) = v;
    *(float4*)(g_hnode + dst) = v;
}

// ------------ last-layer message aggregation ------------
__global__ void __launch_bounds__(256) msg3_k()
{
    __shared__ float snh[32][24];
    __shared__ float sg[576];
    int f = blockIdx.x >> 2, dg = blockIdx.x & 3;
    int tid = threadIdx.x;
    for (int i = tid; i < 768; i += 256) {
        int d = i / 24, w = i - d * 24;
        snh[d][w] = g_nh[(dg * 32 + d) * NCOLS + f * 24 + w];
    }
    for (int i = tid; i < 576; i += 256) sg[i] = g_gate[f * 576 + i];
    __syncthreads();

    int wl = tid & 31, wp = tid >> 5;
    bool ok = wl < 24;
    for (int p = wp; p < 768; p += 8) {
        int dl = p / 24, v = p - dl * 24;
        int d = dg * 32 + dl;
        float s = 0.f;
        if (ok) s = sg[v * 24 + wl] * fmaxf(snh[dl][wl] + g_epre[(size_t)d * ECOLS + f * 576 + v * 24 + wl], 0.f);
#pragma unroll
        for (int o = 16; o; o >>= 1) s += __shfl_xor_sync(0xffffffffu, s, o);
        if (wl == 0) g_mv[d * NCOLS + f * 24 + v] = s;
    }
}

// ------------ GRU elementwise ------------
__global__ void __launch_bounds__(256) gru_k(const int* __restrict__ nnum,
                                             const float* __restrict__ bih,
                                             const float* __restrict__ bhh)
{
    int idx = blockIdx.x * 256 + threadIdx.x;        // < 128*NCOLS
    int j = idx / NCOLS; int col = idx - j * NCOLS;
    float gir = g_gi[j * NCOLS + col]         + bih[j];
    float giz = g_gi[(128 + j) * NCOLS + col] + bih[128 + j];
    float gin = g_gi[(256 + j) * NCOLS + col] + bih[256 + j];
    float ghr = g_gh[j * NCOLS + col]         + bhh[j];
    float ghz = g_gh[(128 + j) * NCOLS + col] + bhh[128 + j];
    float ghn = g_gh[(256 + j) * NCOLS + col] + bhh[256 + j];
    float r = sigm(gir + ghr);
    float z = sigm(giz + ghz);
    float n2 = tanhf(gin + r * ghn);
    float h = g_hnode[idx];
    float hn = (1.f - z) * n2 + z * h;
    int f = col / 24; int n = col - f * 24;
    g_hnode[idx] = (n < nnum[f]) ? hn : g_node0[idx];
}

// ------------ persistent LSTM ------------
__device__ __forceinline__ void group_barrier(int b, unsigned want)
{
    __threadfence();
    __syncthreads();
    if (threadIdx.x == 0) {
        unsigned tk = atomicAdd(&g_cnt2[b], 1u);
        if (tk == 15u) {
            g_cnt2[b] = 0;
            __threadfence();
            atomicExch(&g_sense2[b], want);
        } else {
            unsigned v;
            do {
                asm volatile("ld.acquire.gpu.u32 %0, [%1];" : "=r"(v) : "l"(&g_sense2[b]));
            } while (v != want);
        }
    }
    __syncthreads();
}

__global__ void __launch_bounds__(192) lstm_all_k(const float* __restrict__ Whh)
{
    __shared__ __align__(16) float sWt[128][36];
    __shared__ float sH[128][25];
    __shared__ float sG[32][25];
    int tid = threadIdx.x;
    int rg = blockIdx.x & 15, b = blockIdx.x >> 4;

    for (int i = tid; i < 4096; i += 192) {
        int r = i >> 7, k = i & 127;
        int jg = (r >> 3) * 128 + rg * 8 + (r & 7);
        sWt[k][r] = Whh[jg * 128 + k];
    }
    int tr = tid & 7, tc = tid >> 3;
    int hh = tid / 24, nn = tid - hh * 24;
    int jrow = rg * 8 + hh;
    int scol = b * 24 + nn;
    float creg = 0.f;
    unsigned phase = 0;

    for (int t = 0; t < 32; t++) {
        if (t == 0) {
            for (int i = tid; i < 3200; i += 192) (&sH[0][0])[i] = 0.f;
            __syncthreads();
        } else {
            phase++;
            group_barrier(b, phase & 1u);
            const float* hb = g_h + ((t + 1) & 1) * 24576;
            for (int i = tid; i < 3072; i += 192) {
                int j = i / 24, n2 = i - j * 24;
                sH[j][n2] = __ldcg(hb + j * 192 + b * 24 + n2);
            }
            __syncthreads();
        }

        unsigned long long acc0 = 0ull, acc1 = 0ull;
#pragma unroll 8
        for (int k = 0; k < 128; k++) {
            ulonglong2 av = *(const ulonglong2*)&sWt[k][tr * 4];
            float bv = sH[k][tc];
            unsigned long long bs = pack2(bv, bv);
            ffma2(acc0, av.x, bs);
            ffma2(acc1, av.y, bs);
        }
        float2 u0 = unpack2(acc0), u1 = unpack2(acc1);
        sG[tr * 4 + 0][tc] = u0.x; sG[tr * 4 + 1][tc] = u0.y;
        sG[tr * 4 + 2][tc] = u1.x; sG[tr * 4 + 3][tc] = u1.y;
        __syncthreads();

        int colx = (b * 32 + t) * 24 + nn;
        float ig = sG[hh][nn]      + g_xg[(      jrow) * NCOLS + colx];
        float fg = sG[8 + hh][nn]  + g_xg[(128 + jrow) * NCOLS + colx];
        float gg = sG[16 + hh][nn] + g_xg[(256 + jrow) * NCOLS + colx];
        float og = sG[24 + hh][nn] + g_xg[(384 + jrow) * NCOLS + colx];
        creg = sigm(fg) * creg + sigm(ig) * tanhf(gg);
        float hnew = sigm(og) * tanhf(creg);
        __stcg(g_h + (t & 1) * 24576 + jrow * 192 + scol, hnew);
        g_hist[jrow * 6144 + t * 192 + scol] = hnew;
        __syncthreads();
    }
    phase++;
    group_barrier(b, phase & 1u);
}

// ------------ readout ------------
__global__ void __launch_bounds__(256) readout_k(const float* __restrict__ roW,
                                                 const float* __restrict__ rob,
                                                 const int* __restrict__ nnum,
                                                 float* __restrict__ out)
{
    __shared__ float sH[128][65];
    __shared__ float sRo[6][128];
    __shared__ float sRob[6];
    int tid = threadIdx.x;
    int c0 = blockIdx.x * 64;
    for (int i = tid; i < 8192; i += 256) {
        int j = i >> 6, cc = i & 63;
        sH[j][cc] = g_hist[j * 6144 + c0 + cc];
    }
    for (int i = tid; i < 768; i += 256) sRo[i >> 7][i & 127] = roW[i];
    if (tid < 6) sRob[tid] = rob[tid];
    __syncthreads();
    for (int e = tid; e < 384; e += 256) {
        int cc = e / 6, c = e - cc * 6;
        float s = 0.f;
#pragma unroll 8
        for (int j = 0; j < 128; j++) s += sRo[c][j] * sH[j][cc];
        int ct = c0 + cc;
        int t = ct / 192; int srem = ct - t * 192;
        int b = srem / 24; int n = srem - b * 24;
        int f = b * 32 + t;
        out[(f * 24 + n) * 6 + c] = (n < nnum[f]) ? (s + sRob[c]) : 0.f;
    }
}

// ------------ host launcher ------------
extern "C" void kernel_launch(void* const* d_in, const int* in_sizes, int n_in,
                              void* d_out, int out_size)
{
    const float* node     = (const float*)d_in[0];
    const float* edge     = (const float*)d_in[1];
    const float* link_W1  = (const float*)d_in[2];
    const float* link_b1  = (const float*)d_in[3];
    const float* link_W2  = (const float*)d_in[4];
    const float* link_b2  = (const float*)d_in[5];
    const float* msg_Wh   = (const float*)d_in[6];
    const float* msg_We   = (const float*)d_in[7];
    const float* msg_b    = (const float*)d_in[8];
    const float* gru_Wih  = (const float*)d_in[9];
    const float* gru_Whh  = (const float*)d_in[10];
    const float* gru_bih  = (const float*)d_in[11];
    const float* gru_bhh  = (const float*)d_in[12];
    const float* lstm_Wih = (const float*)d_in[13];
    const float* lstm_Whh = (const float*)d_in[14];
    const float* lstm_bih = (const float*)d_in[15];
    const float* lstm_bhh = (const float*)d_in[16];
    const float* ro_W     = (const float*)d_in[17];
    const float* ro_b     = (const float*)d_in[18];
    const int*   nnum     = (const int*)d_in[19];
    float* out = (float*)d_out;

    float* hnode; cudaGetSymbolAddress((void**)&hnode, g_hnode);
    float* nh;    cudaGetSymbolAddress((void**)&nh,    g_nh);
    float* xg;    cudaGetSymbolAddress((void**)&xg,    g_xg);
    uint4* wA;    cudaGetSymbolAddress((void**)&wA,    g_wA4);

    static int smem_set = 0;
    if (!smem_set) {
        cudaFuncSetAttribute(edge0_k, cudaFuncAttributeMaxDynamicSharedMemorySize, SM_EDGE);
        cudaFuncSetAttribute(recon_k, cudaFuncAttributeMaxDynamicSharedMemorySize, SM_EDGE);
        cudaFuncSetAttribute(hgemm_k, cudaFuncAttributeMaxDynamicSharedMemorySize, SM_HG);
        cudaFuncSetAttribute(gigh_k,  cudaFuncAttributeMaxDynamicSharedMemorySize, SM_HG);
        smem_set = 1;
    }

    const int NTILE = ECOLS / 96;   // 1536
    const int NCT   = NCOLS / 96;   // 64

    // launch order puts recon_k at position 6 (ncu captures launch #6)
    tr_node_k<<<(128 * NCOLS / 4) / 256, 256>>>(node);                       // 1
    prep_a_k<<<72, 256>>>(link_W1, msg_We, msg_Wh, wA);                      // 2
    prep_b_k<<<240, 256>>>(gru_Wih, gru_Whh, lstm_Wih, wA);                  // 3
    edge0_k<<<NTILE, 256, SM_EDGE>>>(edge, link_b1, link_W2, link_b2, msg_b, nnum);  // 4

    for (int p = 0; p < 3; p++) {
        hgemm_k<<<dim3(NCT, 1), 256, SM_HG>>>(wA + 12288, hnode, nullptr, nullptr, nh, NCOLS); // 5
        if (p < 2) {
            recon_k<<<NTILE, 256, SM_EDGE>>>(link_b1, link_W2, link_b2, nnum);                 // 6
        } else {
            msg3_k<<<1024, 256>>>();
        }
        gigh_k<<<dim3(NCT, 6), 256, SM_HG>>>(wA);
        gru_k<<<(128 * NCOLS) / 256, 256>>>(nnum, gru_bih, gru_bhh);
    }

    hgemm_k<<<dim3(NCT, 4), 256, SM_HG>>>(wA + 55296, hnode, lstm_bih, lstm_bhh, xg, NCOLS);
    lstm_all_k<<<128, 192>>>(lstm_Whh);
    readout_k<<<96, 256>>>(ro_W, ro_b, nnum, out);
    (void)in_sizes; (void)n_in; (void)out_size;
}

// round 8
// speedup vs baseline: 1.9794x; 1.0144x over previous
#include <cuda_runtime.h>
#include <cuda_bf16.h>
#include <math.h>
#include <stdint.h>

// ------------ problem constants ------------
#define NFRM   256                  // B*T
#define ECOLS  147456               // NFRM * 576 edge columns
#define NCOLS  6144                 // NFRM * 24 node columns

// ------------ device scratch ------------
__device__ float g_epre  [128 * ECOLS];   // msg_We @ edge + msg_b (loop-invariant)
__device__ float g_gate  [ECOLS];
__device__ float g_node0 [128 * NCOLS];   // transposed node_resnet
__device__ float g_hnode [128 * NCOLS];
__device__ float g_nh    [128 * NCOLS];   // msg_Wh @ h_node
__device__ float g_mv    [128 * NCOLS];
__device__ float g_gi    [384 * NCOLS];
__device__ float g_gh    [384 * NCOLS];
__device__ float g_xg    [512 * NCOLS];   // lstm_Wih @ h_node + bih + bhh
__device__ float g_h     [2 * 128 * 192]; // double-buffered LSTM hidden
__device__ float g_hist  [128 * 6144];    // h history [j][t*192 + b*24 + n]
__device__ unsigned g_cnt2[8];
__device__ unsigned g_sense2[8];
// HMMA A fragments: per m16 block 768 uint4 (24 kk * 32 lanes)
// offsets (uint4): link_W1=0, msg_We=6144, msg_Wh=12288, gru_Wih=18432,
//                  gru_Whh=36864, lstm_Wih=55296  (total 79872)
__device__ uint4 g_wA4[79872];

__device__ __forceinline__ float sigm(float x) { return 1.f / (1.f + expf(-x)); }

__device__ __forceinline__ void ffma2(unsigned long long& acc,
                                      unsigned long long a, unsigned long long b) {
    asm("fma.rn.f32x2 %0, %1, %2, %0;" : "+l"(acc) : "l"(a), "l"(b));
}
__device__ __forceinline__ unsigned long long pack2(float x, float y) {
    unsigned long long r;
    asm("mov.b64 %0, {%1, %2};" : "=l"(r) : "f"(x), "f"(y));
    return r;
}
__device__ __forceinline__ float2 unpack2(unsigned long long v) {
    float2 f;
    asm("mov.b64 {%0, %1}, %2;" : "=f"(f.x), "=f"(f.y) : "l"(v));
    return f;
}
__device__ __forceinline__ void split_bf(float x, __nv_bfloat16& h, __nv_bfloat16& l) {
    h = __float2bfloat16(x);
    l = __float2bfloat16(x - __bfloat162float(h));
}
__device__ __forceinline__ void split_pair(float x0, float x1, unsigned& hw, unsigned& lw) {
    __nv_bfloat16 h0, l0, h1, l1;
    split_bf(x0, h0, l0); split_bf(x1, h1, l1);
    hw = (unsigned)__bfloat16_as_ushort(h0) | ((unsigned)__bfloat16_as_ushort(h1) << 16);
    lw = (unsigned)__bfloat16_as_ushort(l0) | ((unsigned)__bfloat16_as_ushort(l1) << 16);
}
__device__ __forceinline__ uint32_t smem_to_u32(const void* p) {
    uint32_t a;
    asm("{ .reg .u64 t; cvta.to.shared.u64 t, %1; cvt.u32.u64 %0, t; }" : "=r"(a) : "l"(p));
    return a;
}

// ---- HMMA m16n8k16 bf16 ----
__device__ __forceinline__ void mma_bf16(float* c, uint32_t a0, uint32_t a1,
                                         uint32_t a2, uint32_t a3,
                                         uint32_t b0, uint32_t b1) {
    asm volatile(
        "mma.sync.aligned.m16n8k16.row.col.f32.bf16.bf16.f32 "
        "{%0,%1,%2,%3}, {%4,%5,%6,%7}, {%8,%9}, {%0,%1,%2,%3};"
        : "+f"(c[0]), "+f"(c[1]), "+f"(c[2]), "+f"(c[3])
        : "r"(a0), "r"(a1), "r"(a2), "r"(a3), "r"(b0), "r"(b1));
}

// B tile: bf16 [96 rows(n)][264 cols(k: 0-127 hi, 128-255 lo, 8 pad)]
// row pitch 528 B = 132 words; 132 mod 32 = 4 -> ldmatrix conflict-free.
#define BPITCH_W  132       // words per B row
#define BPITCH_B  528
#define SNH_OFF   50688     // float[128*24]
#define SG_OFF    62976     // float[96]
#define SRED_OFF  63360     // float[8][52]
#define SM_EDGE   66688
#define SM_HG     50688

// ------------ prep: pack split-bf16 W (K-stacked [Whi|Whi|Wlo]) into HMMA A-frag layout ------------
__device__ __forceinline__ void prep_one(const float* __restrict__ W, uint4* __restrict__ out,
                                         int gidx)
{
    int mblk = gidx / 768;
    int rem  = gidx - mblk * 768;
    int kk   = rem >> 5;
    int lane = rem & 31;
    int g = lane >> 2, t = lane & 3;
    unsigned regs[4];
#pragma unroll
    for (int r = 0; r < 4; r++) {
        int row = mblk * 16 + g + ((r & 1) ? 8 : 0);
        int k0  = kk * 16 + t * 2 + ((r & 2) ? 8 : 0);
        unsigned pk = 0;
#pragma unroll
        for (int e = 0; e < 2; e++) {
            int ks = k0 + e;
            int region = ks >> 7;
            int kloc = ks & 127;
            float w = W[row * 128 + kloc];
            __nv_bfloat16 h, l; split_bf(w, h, l);
            __nv_bfloat16 b = (region < 2) ? h : l;
            pk |= (unsigned)__bfloat16_as_ushort(b) << (e * 16);
        }
        regs[r] = pk;
    }
    out[gidx] = make_uint4(regs[0], regs[1], regs[2], regs[3]);
}

__global__ void __launch_bounds__(256) prep_a_k(const float* __restrict__ w1,
                                                const float* __restrict__ we,
                                                const float* __restrict__ wh,
                                                uint4* __restrict__ out)
{
    int b = blockIdx.x;
    if (b < 24)      prep_one(w1, out,          b * 256 + threadIdx.x);
    else if (b < 48) prep_one(we, out + 6144,  (b - 24) * 256 + threadIdx.x);
    else             prep_one(wh, out + 12288, (b - 48) * 256 + threadIdx.x);
}
__global__ void __launch_bounds__(256) prep_b_k(const float* __restrict__ wih,
                                                const float* __restrict__ whh,
                                                const float* __restrict__ lih,
                                                uint4* __restrict__ out)
{
    int b = blockIdx.x;
    if (b < 72)       prep_one(wih, out + 18432,  b * 256 + threadIdx.x);
    else if (b < 144) prep_one(whh, out + 36864, (b - 72) * 256 + threadIdx.x);
    else              prep_one(lih, out + 55296, (b - 144) * 256 + threadIdx.x);
}

// ------------ warp GEMM m32 x n48: C[2][6][4] = A(2 m16 blocks) @ B(n-half) over 24 k16 ------------
// A4 = base of the warp's two consecutive m16 blocks; B frag shared by both -> 1 LDSM per MMA.
__device__ __forceinline__ void gemm_m32(float c[2][6][4], const uint4* __restrict__ A4,
                                         uint32_t sbAddr, int lane, int nh)
{
    int midx = lane >> 3, row = lane & 7;
    uint32_t base0 = sbAddr +
        (uint32_t)((nh * 48 + ((midx >> 1) << 3) + row) * BPITCH_B + (midx & 1) * 16);
#pragma unroll
    for (int mb = 0; mb < 2; mb++)
#pragma unroll
        for (int nt = 0; nt < 6; nt++)
#pragma unroll
            for (int r = 0; r < 4; r++) c[mb][nt][r] = 0.f;

#pragma unroll 2
    for (int kk = 0; kk < 24; kk++) {
        uint4 a0 = A4[kk * 32 + lane];
        uint4 a1 = A4[768 + kk * 32 + lane];
        uint32_t kb = (uint32_t)((kk < 16 ? kk : kk - 16) * 32);
#pragma unroll
        for (int j2 = 0; j2 < 3; j2++) {
            uint32_t r0, r1, r2, r3;
            asm volatile("ldmatrix.sync.aligned.m8n8.x4.shared.b16 {%0,%1,%2,%3}, [%4];"
                         : "=r"(r0), "=r"(r1), "=r"(r2), "=r"(r3)
                         : "r"(base0 + (uint32_t)(j2 * 16 * BPITCH_B) + kb));
            mma_bf16(c[0][2 * j2],     a0.x, a0.y, a0.z, a0.w, r0, r1);
            mma_bf16(c[0][2 * j2 + 1], a0.x, a0.y, a0.z, a0.w, r2, r3);
            mma_bf16(c[1][2 * j2],     a1.x, a1.y, a1.z, a1.w, r0, r1);
            mma_bf16(c[1][2 * j2 + 1], a1.x, a1.y, a1.z, a1.w, r2, r3);
        }
    }
}

// ------------ gate epilogue (m32 x n48 tiling) ------------
__device__ __forceinline__ void gate_epi32(float c[2][6][4], char* smem,
                                           const float* __restrict__ lb1,
                                           const float* __restrict__ W2,
                                           const float* __restrict__ b2p,
                                           const int* __restrict__ nnum,
                                           int c0, int f, int off)
{
    int tid = threadIdx.x;
    int w = tid >> 5, lane = tid & 31;
    int mp = w & 3;
    int g = lane >> 2, t = lane & 3;
    float* sRed = (float*)(smem + SRED_OFF);   // [8][52]

    float p0[6], p1[6];
#pragma unroll
    for (int j = 0; j < 6; j++) { p0[j] = 0.f; p1[j] = 0.f; }
#pragma unroll
    for (int mb = 0; mb < 2; mb++) {
        int r0 = mp * 32 + mb * 16 + g;
        float bb0 = lb1[r0], bb8 = lb1[r0 + 8];
        float w0 = W2[r0], w8 = W2[r0 + 8];
#pragma unroll
        for (int j = 0; j < 6; j++) {
            p0[j] += fmaxf(c[mb][j][0] + bb0, 0.f) * w0 + fmaxf(c[mb][j][2] + bb8, 0.f) * w8;
            p1[j] += fmaxf(c[mb][j][1] + bb0, 0.f) * w0 + fmaxf(c[mb][j][3] + bb8, 0.f) * w8;
        }
    }
#pragma unroll
    for (int j = 0; j < 6; j++) {
#pragma unroll
        for (int m = 4; m <= 16; m <<= 1) {
            p0[j] += __shfl_xor_sync(0xffffffffu, p0[j], m);
            p1[j] += __shfl_xor_sync(0xffffffffu, p1[j], m);
        }
    }
    if (g == 0) {
#pragma unroll
        for (int j = 0; j < 6; j++) {
            sRed[w * 52 + j * 8 + t * 2]     = p0[j];
            sRed[w * 52 + j * 8 + t * 2 + 1] = p1[j];
        }
    }
    __syncthreads();
    if (tid < 96) {
        int nh2 = tid / 48, nn = tid - nh2 * 48;
        float s = sRed[(nh2 * 4 + 0) * 52 + nn] + sRed[(nh2 * 4 + 1) * 52 + nn]
                + sRed[(nh2 * 4 + 2) * 52 + nn] + sRed[(nh2 * 4 + 3) * 52 + nn];
        int v = (off + tid) / 24, ww = (off + tid) - v * 24;
        int cnt = nnum[f];
        g_gate[c0 + tid] = (v < cnt && ww < cnt) ? sigm(s + b2p[0]) : 0.f;
    }
}

// ------------ edge0_k: layer-0 gate + epre (two GEMM passes share one B tile) ------------
__global__ void __launch_bounds__(256, 3) edge0_k(const float* __restrict__ edge,
                                                  const float* __restrict__ lb1,
                                                  const float* __restrict__ W2,
                                                  const float* __restrict__ b2p,
                                                  const float* __restrict__ msg_b,
                                                  const int* __restrict__ nnum)
{
    extern __shared__ char smem[];
    uint32_t sbAddr = smem_to_u32(smem);
    unsigned* sBw = (unsigned*)smem;
    int tid = threadIdx.x;
    int c0 = blockIdx.x * 96;
    int f = c0 / 576;
    int off = c0 - f * 576;

    // B conversion, d-pair packed: q = n-quarter, dp = d-pair
    {
        int q = tid >> 6, dp = tid & 63;
        const float* s0 = edge + (size_t)f * 73728 + (2 * dp) * 576 + off + q * 24;
        const float* s1 = s0 + 576;
        for (int i = 0; i < 24; i += 4) {
            float4 x0 = *(const float4*)(s0 + i);
            float4 x1 = *(const float4*)(s1 + i);
            float a0[4] = {x0.x, x0.y, x0.z, x0.w};
            float a1[4] = {x1.x, x1.y, x1.z, x1.w};
#pragma unroll
            for (int j = 0; j < 4; j++) {
                int n = q * 24 + i + j;
                unsigned hw, lw; split_pair(a0[j], a1[j], hw, lw);
                sBw[n * BPITCH_W + dp]      = hw;
                sBw[n * BPITCH_W + 64 + dp] = lw;
            }
        }
    }
    __syncthreads();

    int w = tid >> 5, lane = tid & 31;
    int mp = w & 3, nh = w >> 2;
    int g = lane >> 2, t = lane & 3;
    float c[2][6][4];

    // pass 1: link_W1 -> gate0
    gemm_m32(c, g_wA4 + (2 * mp) * 768, sbAddr, lane, nh);
    gate_epi32(c, smem, lb1, W2, b2p, nnum, c0, f, off);
    __syncthreads();

    // pass 2: msg_We -> epre
    gemm_m32(c, g_wA4 + 6144 + (2 * mp) * 768, sbAddr, lane, nh);
#pragma unroll
    for (int mb = 0; mb < 2; mb++) {
        int r0 = mp * 32 + mb * 16 + g;
        float mb0 = msg_b[r0], mb8 = msg_b[r0 + 8];
#pragma unroll
        for (int j = 0; j < 6; j++) {
            int col = c0 + nh * 48 + j * 8 + t * 2;
            *(float2*)(g_epre + (size_t)r0 * ECOLS + col) =
                make_float2(c[mb][j][0] + mb0, c[mb][j][1] + mb0);
            *(float2*)(g_epre + (size_t)(r0 + 8) * ECOLS + col) =
                make_float2(c[mb][j][2] + mb8, c[mb][j][3] + mb8);
        }
    }
}

// ------------ recon_k: layer p>=1 gate + m_v of layer p-1 (byproduct) ------------
__global__ void __launch_bounds__(256, 3) recon_k(const float* __restrict__ lb1,
                                                  const float* __restrict__ W2,
                                                  const float* __restrict__ b2p,
                                                  const int* __restrict__ nnum)
{
    extern __shared__ char smem[];
    uint32_t sbAddr = smem_to_u32(smem);
    unsigned* sBw = (unsigned*)smem;
    float* snh = (float*)(smem + SNH_OFF);   // [128][24]
    float* sg  = (float*)(smem + SG_OFF);    // [96]
    int tid = threadIdx.x;
    int c0 = blockIdx.x * 96;
    int f = c0 / 576;
    int off = c0 - f * 576;

    for (int i = tid; i < 3072; i += 256) {
        int d = i / 24, w = i - d * 24;
        snh[d * 24 + w] = g_nh[d * NCOLS + f * 24 + w];
    }
    if (tid < 96) sg[tid] = g_gate[c0 + tid];
    __syncthreads();

    // B conversion from reconstruction h_edge = gate * relu(nh + epre); m_v byproduct
    {
        int q = tid >> 6, dp = tid & 63;
        int d0 = 2 * dp, d1 = d0 + 1;
        const float* s0 = g_epre + (size_t)d0 * ECOLS + c0 + q * 24;
        const float* s1 = s0 + ECOLS;
        float sum0 = 0.f, sum1 = 0.f;
        for (int i = 0; i < 24; i += 4) {
            float4 x0 = *(const float4*)(s0 + i);
            float4 x1 = *(const float4*)(s1 + i);
            float a0[4] = {x0.x, x0.y, x0.z, x0.w};
            float a1[4] = {x1.x, x1.y, x1.z, x1.w};
#pragma unroll
            for (int j = 0; j < 4; j++) {
                int w = i + j;
                int n = q * 24 + w;
                float gv = sg[n];
                float v0 = gv * fmaxf(snh[d0 * 24 + w] + a0[j], 0.f);
                float v1 = gv * fmaxf(snh[d1 * 24 + w] + a1[j], 0.f);
                sum0 += v0; sum1 += v1;
                unsigned hw, lw; split_pair(v0, v1, hw, lw);
                sBw[n * BPITCH_W + dp]      = hw;
                sBw[n * BPITCH_W + 64 + dp] = lw;
            }
        }
        int v = off / 24 + q;
        g_mv[d0 * NCOLS + f * 24 + v] = sum0;
        g_mv[d1 * NCOLS + f * 24 + v] = sum1;
    }
    __syncthreads();

    int w = tid >> 5, lane = tid & 31;
    int mp = w & 3, nh = w >> 2;
    float c[2][6][4];
    gemm_m32(c, g_wA4 + (2 * mp) * 768, sbAddr, lane, nh);
    gate_epi32(c, smem, lb1, W2, b2p, nnum, c0, f, off);
}

// ------------ shared hgemm body (m32 x n48 tiling) ------------
__device__ __forceinline__ void hgemm_body(const uint4* __restrict__ Afrag, int mrowblk,
                                           const float* __restrict__ X,
                                           const float* __restrict__ bias,
                                           const float* __restrict__ bias2,
                                           float* __restrict__ Y, int cols, int c0,
                                           char* smem, uint32_t sbAddr)
{
    unsigned* sBw = (unsigned*)smem;
    int tid = threadIdx.x;
    {
        int q = tid >> 6, dp = tid & 63;
        const float* s0 = X + (size_t)(2 * dp) * cols + c0 + q * 24;
        const float* s1 = s0 + cols;
        for (int i = 0; i < 24; i += 4) {
            float4 x0 = *(const float4*)(s0 + i);
            float4 x1 = *(const float4*)(s1 + i);
            float a0[4] = {x0.x, x0.y, x0.z, x0.w};
            float a1[4] = {x1.x, x1.y, x1.z, x1.w};
#pragma unroll
            for (int j = 0; j < 4; j++) {
                int n = q * 24 + i + j;
                unsigned hw, lw; split_pair(a0[j], a1[j], hw, lw);
                sBw[n * BPITCH_W + dp]      = hw;
                sBw[n * BPITCH_W + 64 + dp] = lw;
            }
        }
    }
    __syncthreads();

    int w = tid >> 5, lane = tid & 31;
    int mp = w & 3, nh = w >> 2;
    int g = lane >> 2, t = lane & 3;
    float c[2][6][4];
    gemm_m32(c, Afrag + (mrowblk * 8 + 2 * mp) * 768, sbAddr, lane, nh);

#pragma unroll
    for (int mb = 0; mb < 2; mb++) {
        int r0 = mrowblk * 128 + mp * 32 + mb * 16 + g;
        float b0v = (bias ? bias[r0] : 0.f) + (bias2 ? bias2[r0] : 0.f);
        float b8v = (bias ? bias[r0 + 8] : 0.f) + (bias2 ? bias2[r0 + 8] : 0.f);
#pragma unroll
        for (int j = 0; j < 6; j++) {
            int col = c0 + nh * 48 + j * 8 + t * 2;
            *(float2*)(Y + (size_t)r0 * cols + col) =
                make_float2(c[mb][j][0] + b0v, c[mb][j][1] + b0v);
            *(float2*)(Y + (size_t)(r0 + 8) * cols + col) =
                make_float2(c[mb][j][2] + b8v, c[mb][j][3] + b8v);
        }
    }
}

__global__ void __launch_bounds__(256, 3) hgemm_k(const uint4* __restrict__ Afrag,
                                                  const float* __restrict__ X,
                                                  const float* __restrict__ bias,
                                                  const float* __restrict__ bias2,
                                                  float* __restrict__ Y, int cols)
{
    extern __shared__ char smem[];
    hgemm_body(Afrag, blockIdx.y, X, bias, bias2, Y, cols, blockIdx.x * 96,
               smem, smem_to_u32(smem));
}

// gi and gh in one launch: y<3 -> gi, y>=3 -> gh
__global__ void __launch_bounds__(256, 3) gigh_k(const uint4* __restrict__ wA)
{
    extern __shared__ char smem[];
    int by = blockIdx.y;
    if (by < 3)
        hgemm_body(wA + 18432, by, g_mv, nullptr, nullptr, g_gi, NCOLS,
                   blockIdx.x * 96, smem, smem_to_u32(smem));
    else
        hgemm_body(wA + 36864, by - 3, g_hnode, nullptr, nullptr, g_gh, NCOLS,
                   blockIdx.x * 96, smem, smem_to_u32(smem));
}

// ------------ node transpose ------------
__global__ void __launch_bounds__(256) tr_node_k(const float* __restrict__ in)
{
    int o4 = blockIdx.x * 256 + threadIdx.x;         // < 128*NCOLS/4
    int d = o4 / 1536; int c4 = o4 - d * 1536;
    int f = c4 / 6;    int n4 = c4 - f * 6;
    float4 v = *(const float4*)(in + f * 3072 + d * 24 + n4 * 4);
    int dst = d * NCOLS + f * 24 + n4 * 4;
    *(float4*)(g_node0 + dst) = v;
    *(float4*)(g_hnode + dst) = v;
}

// ------------ last-layer message aggregation ------------
__global__ void __launch_bounds__(256) msg3_k()
{
    __shared__ float snh[32][24];
    __shared__ float sg[576];
    int f = blockIdx.x >> 2, dg = blockIdx.x & 3;
    int tid = threadIdx.x;
    for (int i = tid; i < 768; i += 256) {
        int d = i / 24, w = i - d * 24;
        snh[d][w] = g_nh[(dg * 32 + d) * NCOLS + f * 24 + w];
    }
    for (int i = tid; i < 576; i += 256) sg[i] = g_gate[f * 576 + i];
    __syncthreads();

    int wl = tid & 31, wp = tid >> 5;
    bool ok = wl < 24;
    for (int p = wp; p < 768; p += 8) {
        int dl = p / 24, v = p - dl * 24;
        int d = dg * 32 + dl;
        float s = 0.f;
        if (ok) s = sg[v * 24 + wl] * fmaxf(snh[dl][wl] + g_epre[(size_t)d * ECOLS + f * 576 + v * 24 + wl], 0.f);
#pragma unroll
        for (int o = 16; o; o >>= 1) s += __shfl_xor_sync(0xffffffffu, s, o);
        if (wl == 0) g_mv[d * NCOLS + f * 24 + v] = s;
    }
}

// ------------ GRU elementwise ------------
__global__ void __launch_bounds__(256) gru_k(const int* __restrict__ nnum,
                                             const float* __restrict__ bih,
                                             const float* __restrict__ bhh)
{
    int idx = blockIdx.x * 256 + threadIdx.x;        // < 128*NCOLS
    int j = idx / NCOLS; int col = idx - j * NCOLS;
    float gir = g_gi[j * NCOLS + col]         + bih[j];
    float giz = g_gi[(128 + j) * NCOLS + col] + bih[128 + j];
    float gin = g_gi[(256 + j) * NCOLS + col] + bih[256 + j];
    float ghr = g_gh[j * NCOLS + col]         + bhh[j];
    float ghz = g_gh[(128 + j) * NCOLS + col] + bhh[128 + j];
    float ghn = g_gh[(256 + j) * NCOLS + col] + bhh[256 + j];
    float r = sigm(gir + ghr);
    float z = sigm(giz + ghz);
    float n2 = tanhf(gin + r * ghn);
    float h = g_hnode[idx];
    float hn = (1.f - z) * n2 + z * h;
    int f = col / 24; int n = col - f * 24;
    g_hnode[idx] = (n < nnum[f]) ? hn : g_node0[idx];
}

// ------------ persistent LSTM ------------
__device__ __forceinline__ void group_barrier(int b, unsigned want)
{
    __threadfence();
    __syncthreads();
    if (threadIdx.x == 0) {
        unsigned tk = atomicAdd(&g_cnt2[b], 1u);
        if (tk == 15u) {
            g_cnt2[b] = 0;
            __threadfence();
            atomicExch(&g_sense2[b], want);
        } else {
            unsigned v;
            do {
                asm volatile("ld.acquire.gpu.u32 %0, [%1];" : "=r"(v) : "l"(&g_sense2[b]));
            } while (v != want);
        }
    }
    __syncthreads();
}

__global__ void __launch_bounds__(192) lstm_all_k(const float* __restrict__ Whh)
{
    __shared__ __align__(16) float sWt[128][36];
    __shared__ float sH[128][25];
    __shared__ float sG[32][25];
    int tid = threadIdx.x;
    int rg = blockIdx.x & 15, b = blockIdx.x >> 4;

    for (int i = tid; i < 4096; i += 192) {
        int r = i >> 7, k = i & 127;
        int jg = (r >> 3) * 128 + rg * 8 + (r & 7);
        sWt[k][r] = Whh[jg * 128 + k];
    }
    int tr = tid & 7, tc = tid >> 3;
    int hh = tid / 24, nn = tid - hh * 24;
    int jrow = rg * 8 + hh;
    int scol = b * 24 + nn;
    float creg = 0.f;
    unsigned phase = 0;

    for (int t = 0; t < 32; t++) {
        if (t == 0) {
            for (int i = tid; i < 3200; i += 192) (&sH[0][0])[i] = 0.f;
            __syncthreads();
        } else {
            phase++;
            group_barrier(b, phase & 1u);
            const float* hb = g_h + ((t + 1) & 1) * 24576;
            for (int i = tid; i < 3072; i += 192) {
                int j = i / 24, n2 = i - j * 24;
                sH[j][n2] = __ldcg(hb + j * 192 + b * 24 + n2);
            }
            __syncthreads();
        }

        unsigned long long acc0 = 0ull, acc1 = 0ull;
#pragma unroll 8
        for (int k = 0; k < 128; k++) {
            ulonglong2 av = *(const ulonglong2*)&sWt[k][tr * 4];
            float bv = sH[k][tc];
            unsigned long long bs = pack2(bv, bv);
            ffma2(acc0, av.x, bs);
            ffma2(acc1, av.y, bs);
        }
        float2 u0 = unpack2(acc0), u1 = unpack2(acc1);
        sG[tr * 4 + 0][tc] = u0.x; sG[tr * 4 + 1][tc] = u0.y;
        sG[tr * 4 + 2][tc] = u1.x; sG[tr * 4 + 3][tc] = u1.y;
        __syncthreads();

        int colx = (b * 32 + t) * 24 + nn;
        float ig = sG[hh][nn]      + g_xg[(      jrow) * NCOLS + colx];
        float fg = sG[8 + hh][nn]  + g_xg[(128 + jrow) * NCOLS + colx];
        float gg = sG[16 + hh][nn] + g_xg[(256 + jrow) * NCOLS + colx];
        float og = sG[24 + hh][nn] + g_xg[(384 + jrow) * NCOLS + colx];
        creg = sigm(fg) * creg + sigm(ig) * tanhf(gg);
        float hnew = sigm(og) * tanhf(creg);
        __stcg(g_h + (t & 1) * 24576 + jrow * 192 + scol, hnew);
        g_hist[jrow * 6144 + t * 192 + scol] = hnew;
        __syncthreads();
    }
    phase++;
    group_barrier(b, phase & 1u);
}

// ------------ readout ------------
__global__ void __launch_bounds__(256) readout_k(const float* __restrict__ roW,
                                                 const float* __restrict__ rob,
                                                 const int* __restrict__ nnum,
                                                 float* __restrict__ out)
{
    __shared__ float sH[128][65];
    __shared__ float sRo[6][128];
    __shared__ float sRob[6];
    int tid = threadIdx.x;
    int c0 = blockIdx.x * 64;
    for (int i = tid; i < 8192; i += 256) {
        int j = i >> 6, cc = i & 63;
        sH[j][cc] = g_hist[j * 6144 + c0 + cc];
    }
    for (int i = tid; i < 768; i += 256) sRo[i >> 7][i & 127] = roW[i];
    if (tid < 6) sRob[tid] = rob[tid];
    __syncthreads();
    for (int e = tid; e < 384; e += 256) {
        int cc = e / 6, c = e - cc * 6;
        float s = 0.f;
#pragma unroll 8
        for (int j = 0; j < 128; j++) s += sRo[c][j] * sH[j][cc];
        int ct = c0 + cc;
        int t = ct / 192; int srem = ct - t * 192;
        int b = srem / 24; int n = srem - b * 24;
        int f = b * 32 + t;
        out[(f * 24 + n) * 6 + c] = (n < nnum[f]) ? (s + sRob[c]) : 0.f;
    }
}

// ------------ host launcher ------------
extern "C" void kernel_launch(void* const* d_in, const int* in_sizes, int n_in,
                              void* d_out, int out_size)
{
    const float* node     = (const float*)d_in[0];
    const float* edge     = (const float*)d_in[1];
    const float* link_W1  = (const float*)d_in[2];
    const float* link_b1  = (const float*)d_in[3];
    const float* link_W2  = (const float*)d_in[4];
    const float* link_b2  = (const float*)d_in[5];
    const float* msg_Wh   = (const float*)d_in[6];
    const float* msg_We   = (const float*)d_in[7];
    const float* msg_b    = (const float*)d_in[8];
    const float* gru_Wih  = (const float*)d_in[9];
    const float* gru_Whh  = (const float*)d_in[10];
    const float* gru_bih  = (const float*)d_in[11];
    const float* gru_bhh  = (const float*)d_in[12];
    const float* lstm_Wih = (const float*)d_in[13];
    const float* lstm_Whh = (const float*)d_in[14];
    const float* lstm_bih = (const float*)d_in[15];
    const float* lstm_bhh = (const float*)d_in[16];
    const float* ro_W     = (const float*)d_in[17];
    const float* ro_b     = (const float*)d_in[18];
    const int*   nnum     = (const int*)d_in[19];
    float* out = (float*)d_out;

    float* hnode; cudaGetSymbolAddress((void**)&hnode, g_hnode);
    float* nh;    cudaGetSymbolAddress((void**)&nh,    g_nh);
    float* xg;    cudaGetSymbolAddress((void**)&xg,    g_xg);
    uint4* wA;    cudaGetSymbolAddress((void**)&wA,    g_wA4);

    static int smem_set = 0;
    if (!smem_set) {
        cudaFuncSetAttribute(edge0_k, cudaFuncAttributeMaxDynamicSharedMemorySize, SM_EDGE);
        cudaFuncSetAttribute(recon_k, cudaFuncAttributeMaxDynamicSharedMemorySize, SM_EDGE);
        cudaFuncSetAttribute(hgemm_k, cudaFuncAttributeMaxDynamicSharedMemorySize, SM_HG);
        cudaFuncSetAttribute(gigh_k,  cudaFuncAttributeMaxDynamicSharedMemorySize, SM_HG);
        smem_set = 1;
    }

    const int NTILE = ECOLS / 96;   // 1536
    const int NCT   = NCOLS / 96;   // 64

    // launch order puts recon_k at position 6 (ncu captures launch #6)
    tr_node_k<<<(128 * NCOLS / 4) / 256, 256>>>(node);                       // 1
    prep_a_k<<<72, 256>>>(link_W1, msg_We, msg_Wh, wA);                      // 2
    prep_b_k<<<240, 256>>>(gru_Wih, gru_Whh, lstm_Wih, wA);                  // 3
    edge0_k<<<NTILE, 256, SM_EDGE>>>(edge, link_b1, link_W2, link_b2, msg_b, nnum);  // 4

    for (int p = 0; p < 3; p++) {
        hgemm_k<<<dim3(NCT, 1), 256, SM_HG>>>(wA + 12288, hnode, nullptr, nullptr, nh, NCOLS); // 5
        if (p < 2) {
            recon_k<<<NTILE, 256, SM_EDGE>>>(link_b1, link_W2, link_b2, nnum);                 // 6
        } else {
            msg3_k<<<1024, 256>>>();
        }
        gigh_k<<<dim3(NCT, 6), 256, SM_HG>>>(wA);
        gru_k<<<(128 * NCOLS) / 256, 256>>>(nnum, gru_bih, gru_bhh);
    }

    hgemm_k<<<dim3(NCT, 4), 256, SM_HG>>>(wA + 55296, hnode, lstm_bih, lstm_bhh, xg, NCOLS);
    lstm_all_k<<<128, 192>>>(lstm_Whh);
    readout_k<<<96, 256>>>(ro_W, ro_b, nnum, out);
    (void)in_sizes; (void)n_in; (void)out_size;
}